// round 5
// baseline (speedup 1.0000x reference)
#include <cuda_runtime.h>
#include <math.h>

// Fixed problem shapes
#define N_NODES 50000
#define N_EDGES 3200000
#define F_IN    8      // 4*NT
#define H1      64
#define NPB     8      // nodes per block (50000 % 8 == 0)
#define NBLK    (N_NODES / NPB)   // 6250
#define TPB     256
#define N_ITERS 8
#define FULLM   0xffffffffu

typedef unsigned long long ull;

// ---------------- packed f32x2 helpers (Blackwell FFMA2) ----------------
__device__ __forceinline__ ull ffma2(ull a, ull b, ull c) {
    ull d;
    asm("fma.rn.f32x2 %0, %1, %2, %3;" : "=l"(d) : "l"(a), "l"(b), "l"(c));
    return d;
}
__device__ __forceinline__ ull packf2(float lo, float hi) {
    ull d;
    asm("mov.b64 %0, {%1, %2};" : "=l"(d) : "f"(lo), "f"(hi));
    return d;
}
__device__ __forceinline__ void unpackf2(ull v, float& lo, float& hi) {
    asm("mov.b64 {%0, %1}, %2;" : "=f"(lo), "=f"(hi) : "l"(v));
}

// ---------------- device scratch (static; no allocation allowed) ----------------
__device__ float g_x0[N_NODES * F_IN];
__device__ float g_x1[N_NODES * F_IN];
__device__ int   g_hist[N_NODES];
__device__ int   g_rowptr[N_NODES + 1];
__device__ int   g_offs[N_NODES];
__device__ int   g_srcs[N_EDGES];
__device__ int   g_dsts[N_EDGES];
__device__ float g_eas[(long long)N_EDGES * 8];   // sorted edge_attr, padded to 8 floats

// prepared weights for the edge MLP
__device__ float g_W1[H1 * 16];   // [j][k]: k<13 -> w1_0[k][j], k==13 -> b1_0[j], else 0
__device__ float g_W2T[H1 * H1];  // [j][k] = w1_1[k][j]
__device__ float g_b11[H1];

// ---------------- weight preparation ----------------
__global__ void prep_kernel(const float* __restrict__ w10, const float* __restrict__ b10,
                            const float* __restrict__ w11, const float* __restrict__ b11) {
    int t = blockIdx.x * blockDim.x + threadIdx.x;
    if (t < H1 * 16) {
        int j = t >> 4, k = t & 15;
        float v = 0.f;
        if (k < 13)       v = w10[k * H1 + j];
        else if (k == 13) v = b10[j];
        g_W1[t] = v;
    }
    if (t < H1 * H1) {
        int j = t >> 6, k = t & 63;
        g_W2T[t] = w11[k * H1 + j];
    }
    if (t < H1) g_b11[t] = b11[t];
}

// ---------------- sorting pipeline (runs once per launch) ----------------
__global__ void zero_hist_kernel() {
    int i = blockIdx.x * blockDim.x + threadIdx.x;
    if (i < N_NODES) g_hist[i] = 0;
}

__global__ void hist_kernel(const int* __restrict__ eidx) {
    int i = blockIdx.x * blockDim.x + threadIdx.x;
    if (i < N_EDGES) atomicAdd(&g_hist[eidx[N_EDGES + i]], 1);
}

// single-block exclusive scan over g_hist -> g_rowptr, g_offs
__global__ void scan_kernel() {
    __shared__ int swarp[16];
    __shared__ int srun;
    int tid = threadIdx.x, lane = tid & 31, wid = tid >> 5;
    if (tid == 0) srun = 0;
    __syncthreads();
    const int CH = (N_NODES + 511) / 512;
    for (int c = 0; c < CH; c++) {
        int i = c * 512 + tid;
        int orig = (i < N_NODES) ? g_hist[i] : 0;
        int v = orig;
#pragma unroll
        for (int off = 1; off < 32; off <<= 1) {
            int n = __shfl_up_sync(FULLM, v, off);
            if (lane >= off) v += n;
        }
        if (lane == 31) swarp[wid] = v;
        __syncthreads();
        if (wid == 0) {
            int w = (lane < 16) ? swarp[lane] : 0;
#pragma unroll
            for (int off = 1; off < 16; off <<= 1) {
                int n = __shfl_up_sync(FULLM, w, off);
                if (lane >= off) w += n;
            }
            if (lane < 16) swarp[lane] = w;
        }
        __syncthreads();
        int base = (wid > 0) ? swarp[wid - 1] : 0;
        int incl = v + base;           // inclusive within chunk
        int run = srun;
        int excl = run + incl - orig;
        if (i < N_NODES) { g_rowptr[i] = excl; g_offs[i] = excl; }
        __syncthreads();
        if (tid == 511) srun = run + incl;
        __syncthreads();
    }
    if (threadIdx.x == 0) g_rowptr[N_NODES] = N_EDGES;
}

__global__ void scatter_kernel(const float* __restrict__ ea, const int* __restrict__ eidx) {
    int i = blockIdx.x * blockDim.x + threadIdx.x;
    if (i >= N_EDGES) return;
    int d = eidx[N_EDGES + i];
    int pos = atomicAdd(&g_offs[d], 1);
    g_srcs[pos] = eidx[i];
    g_dsts[pos] = d;
    const float* a = ea + (long long)i * 5;
    float* o = g_eas + (long long)pos * 8;
    o[0] = a[0]; o[1] = a[1]; o[2] = a[2]; o[3] = a[3]; o[4] = a[4];
}

// ---------------- fused iteration kernel ----------------
// Block owns nodes [8b, 8b+8) and their contiguous dst-sorted edge range.
// Edge MLP (packed f32x2) -> warp segmented suffix-max -> leader smem atomicMax -> node MLP.
__global__ __launch_bounds__(TPB, 1)
void fused_kernel(const float* __restrict__ x, float* __restrict__ y,
                  const float* __restrict__ w20, const float* __restrict__ b20,
                  const float* __restrict__ w21, const float* __restrict__ b21) {
    __shared__ float sW1[H1 * 16];
    __shared__ float sW2[H1 * H1];
    __shared__ float sb1[H1];
    __shared__ float sW3[72 * 32];
    __shared__ float sb20[32];
    __shared__ float sW4[32 * 5];
    __shared__ float sb21[8];
    __shared__ int   saccum[NPB * H1];
    __shared__ float sxn[NPB * F_IN];
    __shared__ float sh2[NPB * 32];
    __shared__ float so[NPB * 5];

    int tid = threadIdx.x;
    for (int i = tid; i < H1 * 16; i += TPB) sW1[i] = g_W1[i];
    for (int i = tid; i < H1 * H1; i += TPB) sW2[i] = g_W2T[i];
    if (tid < H1) sb1[tid] = g_b11[tid];
    for (int i = tid; i < 72 * 32; i += TPB) sW3[i] = w20[i];
    for (int i = tid; i < 32 * 5; i += TPB) sW4[i] = w21[i];
    if (tid < 32) sb20[tid] = b20[tid];
    if (tid < 5)  sb21[tid] = b21[tid];
    for (int i = tid; i < NPB * H1; i += TPB) saccum[i] = 0;
    int nodeBase = blockIdx.x * NPB;
    if (tid < NPB * F_IN) sxn[tid] = x[nodeBase * F_IN + tid];
    __syncthreads();

    const int e0 = g_rowptr[nodeBase];
    const int e1 = g_rowptr[nodeBase + NPB];
    const int lane = tid & 31;

    for (int eb = e0; eb < e1; eb += TPB) {
        int e = eb + tid;
        bool act = e < e1;
        int dstL = 0x7fffffff;
        ull tp[8];
#pragma unroll
        for (int k = 0; k < 8; k++) tp[k] = 0ULL;
        if (act) {
            int src = g_srcs[e];
            dstL = g_dsts[e] - nodeBase;
            const float4* xr = reinterpret_cast<const float4*>(x + (long long)src * F_IN);
            float4 xa = __ldg(xr);
            float4 xb = __ldg(xr + 1);
            const float* a = g_eas + (long long)e * 8;
            float4 a4 = *reinterpret_cast<const float4*>(a);
            float a5 = a[4];
            tp[0] = packf2(xa.x, xa.y);
            tp[1] = packf2(xa.z, xa.w);
            tp[2] = packf2(xb.x, xb.y);
            tp[3] = packf2(xb.z, xb.w);
            tp[4] = packf2(a4.x, a4.y);
            tp[5] = packf2(a4.z, a4.w);
            tp[6] = packf2(a5, 1.f);   // bias slot
            // tp[7] = 0
        }

        // GEMM1 (packed): h pairs (h[2jp], h[2jp+1])
        ull h[32];
#pragma unroll
        for (int jp = 0; jp < 32; jp++) {
            const ulonglong2* w0 = reinterpret_cast<const ulonglong2*>(sW1 + (2 * jp) * 16);
            const ulonglong2* w1 = reinterpret_cast<const ulonglong2*>(sW1 + (2 * jp + 1) * 16);
            ull a0 = 0ULL, a1 = 0ULL;
#pragma unroll
            for (int q = 0; q < 4; q++) {
                ulonglong2 v0 = w0[q];
                a0 = ffma2(tp[2 * q], v0.x, a0);
                a0 = ffma2(tp[2 * q + 1], v0.y, a0);
                ulonglong2 v1 = w1[q];
                a1 = ffma2(tp[2 * q], v1.x, a1);
                a1 = ffma2(tp[2 * q + 1], v1.y, a1);
            }
            float l0, h0, l1, hh1;
            unpackf2(a0, l0, h0);
            unpackf2(a1, l1, hh1);
            float r0 = fmaxf(l0 + h0, 0.f);
            float r1 = fmaxf(l1 + hh1, 0.f);
            h[jp] = packf2(r0, r1);
        }

        // segment masks (lanes are dst-sorted)
        int d1 = __shfl_down_sync(FULLM, dstL, 1);  bool s1 = (lane <= 30) && (d1 == dstL);
        int d2 = __shfl_down_sync(FULLM, dstL, 2);  bool s2 = (lane <= 29) && (d2 == dstL);
        int d4 = __shfl_down_sync(FULLM, dstL, 4);  bool s4 = (lane <= 27) && (d4 == dstL);
        int d8 = __shfl_down_sync(FULLM, dstL, 8);  bool s8 = (lane <= 23) && (d8 == dstL);
        int d16 = __shfl_down_sync(FULLM, dstL, 16); bool s16 = (lane <= 15) && (d16 == dstL);
        int dp = __shfl_up_sync(FULLM, dstL, 1);
        bool doAtom = ((lane == 0) || (dp != dstL)) && act;
        int abase = dstL * H1;

        // GEMM2 (packed) in groups of 8 + segmented suffix-max + leader smem atomics
#pragma unroll 1
        for (int jb = 0; jb < H1; jb += 8) {
            float m[8];
#pragma unroll
            for (int jj = 0; jj < 8; jj++) {
                const ulonglong2* w = reinterpret_cast<const ulonglong2*>(sW2 + (jb + jj) * H1);
                ull acc = packf2(sb1[jb + jj], 0.f);
#pragma unroll
                for (int q = 0; q < 16; q++) {
                    ulonglong2 wv = w[q];
                    acc = ffma2(h[2 * q], wv.x, acc);
                    acc = ffma2(h[2 * q + 1], wv.y, acc);
                }
                float lo, hi;
                unpackf2(acc, lo, hi);
                m[jj] = fmaxf(lo + hi, 0.f);
            }
#pragma unroll
            for (int jj = 0; jj < 8; jj++) {
                float v = m[jj], v2;
                v2 = __shfl_down_sync(FULLM, v, 1);  v = fmaxf(v, s1 ? v2 : 0.f);
                v2 = __shfl_down_sync(FULLM, v, 2);  v = fmaxf(v, s2 ? v2 : 0.f);
                v2 = __shfl_down_sync(FULLM, v, 4);  v = fmaxf(v, s4 ? v2 : 0.f);
                v2 = __shfl_down_sync(FULLM, v, 8);  v = fmaxf(v, s8 ? v2 : 0.f);
                v2 = __shfl_down_sync(FULLM, v, 16); v = fmaxf(v, s16 ? v2 : 0.f);
                if (doAtom) atomicMax(&saccum[abase + jb + jj], __float_as_int(v));
            }
        }
    }
    __syncthreads();

    // ---- node MLP for the block's 8 nodes ----
    {
        int s = tid >> 5, j = tid & 31;   // warp s handles node s
        float acc = sb20[j];
#pragma unroll
        for (int k = 0; k < F_IN; k++)
            acc += sxn[s * F_IN + k] * sW3[k * 32 + j];
#pragma unroll 8
        for (int k = 0; k < H1; k++)
            acc += __int_as_float(saccum[s * H1 + k]) * sW3[(F_IN + k) * 32 + j];
        sh2[s * 32 + j] = fmaxf(acc, 0.f);
    }
    __syncthreads();
    if (tid < NPB * 5) {
        int s = tid / 5, jo = tid % 5;
        float acc = sb21[jo];
#pragma unroll
        for (int k = 0; k < 32; k++)
            acc += sh2[s * 32 + k] * sW4[k * 5 + jo];
        so[tid] = acc;
    }
    __syncthreads();
    if (tid < NPB) {
        int n = nodeBase + tid;
        float l  = so[tid * 5 + 0];
        float c1 = so[tid * 5 + 1];
        float c2 = so[tid * 5 + 2];
        float c3 = so[tid * 5 + 3];
        float c4 = so[tid * 5 + 4];
        float nor = sqrtf(c1 * c1 + c2 * c2 + c3 * c3 + c4 * c4);
        float dd = fmaxf(1.f, nor);
        float* yr = y + (long long)n * F_IN;
        yr[0] = l;
        yr[1] = c1 / dd;
        yr[2] = c2 / dd;
        yr[3] = c3 / dd;
        yr[4] = c4 / dd;
        yr[5] = sxn[tid * F_IN + 0];
        yr[6] = sxn[tid * F_IN + 1];
        yr[7] = sxn[tid * F_IN + 2];
    }
}

// ---------------- host ----------------
extern "C" void kernel_launch(void* const* d_in, const int* in_sizes, int n_in,
                              void* d_out, int out_size) {
    const float* x_in = (const float*)d_in[0];
    const float* ea   = (const float*)d_in[1];
    const int*   ei   = (const int*)d_in[2];
    const float* w10  = (const float*)d_in[3];
    const float* b10  = (const float*)d_in[4];
    const float* w11  = (const float*)d_in[5];
    const float* b11  = (const float*)d_in[6];
    const float* w20  = (const float*)d_in[7];
    const float* b20  = (const float*)d_in[8];
    const float* w21  = (const float*)d_in[9];
    const float* b21  = (const float*)d_in[10];

    float* xb[2];
    cudaGetSymbolAddress((void**)&xb[0], g_x0);
    cudaGetSymbolAddress((void**)&xb[1], g_x1);

    prep_kernel<<<16, 256>>>(w10, b10, w11, b11);
    zero_hist_kernel<<<(N_NODES + 255) / 256, 256>>>();
    hist_kernel<<<(N_EDGES + 255) / 256, 256>>>(ei);
    scan_kernel<<<1, 512>>>();
    scatter_kernel<<<(N_EDGES + 255) / 256, 256>>>(ea, ei);

    const float* xin = x_in;
    for (int it = 0; it < N_ITERS; it++) {
        float* yout = (it == N_ITERS - 1) ? (float*)d_out : xb[it & 1];
        fused_kernel<<<NBLK, TPB>>>(xin, yout, w20, b20, w21, b21);
        xin = yout;
    }
}

// round 7
// speedup vs baseline: 1.7714x; 1.7714x over previous
#include <cuda_runtime.h>
#include <math.h>

// Fixed problem shapes
#define N_NODES 50000
#define N_EDGES 3200000
#define F_IN    8      // 4*NT
#define H1      64
#define NPB     8      // nodes per block
#define NBLK    (N_NODES / NPB)   // 6250
#define TPB     256
#define N_ITERS 8
#define FULLM   0xffffffffu

// per-warp scratch (floats): A1 = 32x20 (staged inputs), h = 32x68 (GEMM1 out)
// msg tile 32x66 overlays [0..2112)
#define A1_STRIDE 20
#define H_STRIDE  68
#define MSG_STRIDE 66
#define SCR_A1    0
#define SCR_H     640
#define SCR_SZ    2816    // 640 + 32*68
// dynamic smem layout (floats): W1f [0,2048) | W2f [2048,10240) | scratch 8*2816
#define DYN_W1F   0
#define DYN_W2F   2048
#define DYN_SCR   10240
#define DYN_FLOATS (10240 + 8 * SCR_SZ)   // 32768 floats = 128KB

// ---------------- device scratch ----------------
__device__ float g_x0[N_NODES * F_IN];
__device__ float g_x1[N_NODES * F_IN];
__device__ int   g_hist[N_NODES];
__device__ int   g_rowptr[N_NODES + 1];
__device__ int   g_offs[N_NODES];
__device__ int   g_srcs[N_EDGES];
__device__ int   g_dsts[N_EDGES];
__device__ float g_eas[(long long)N_EDGES * 8];

// fragment-ordered weights: uint4 = {b0_hi, b1_hi, b0_lo, b1_lo}
__device__ uint4 g_W1f[16 * 32];   // pos = n*2+k  (n<8, k<2)
__device__ uint4 g_W2f[64 * 32];   // pos = n*8+k  (n<8, k<8)

// ---------------- tf32 helpers ----------------
__device__ __forceinline__ unsigned tf32_of(float x) {
    unsigned u;
    asm("cvt.rna.tf32.f32 %0, %1;" : "=r"(u) : "f"(x));
    return u;
}
__device__ __forceinline__ void tf32_split(float x, unsigned& hi, unsigned& lo) {
    hi = tf32_of(x);
    lo = tf32_of(x - __uint_as_float(hi));
}
__device__ __forceinline__ void mma_tf32(float& c0, float& c1, float& c2, float& c3,
                                         unsigned a0, unsigned a1, unsigned a2, unsigned a3,
                                         unsigned b0, unsigned b1) {
    asm("mma.sync.aligned.m16n8k8.row.col.f32.tf32.tf32.f32 "
        "{%0,%1,%2,%3}, {%4,%5,%6,%7}, {%8,%9}, {%0,%1,%2,%3};"
        : "+f"(c0), "+f"(c1), "+f"(c2), "+f"(c3)
        : "r"(a0), "r"(a1), "r"(a2), "r"(a3), "r"(b0), "r"(b1));
}

// ---------------- weight fragment preparation ----------------
__device__ __forceinline__ float w1eff(const float* w10, const float* b10, int k, int j) {
    if (k < 13) return w10[k * 64 + j];
    if (k == 13) return b10[j];
    return 0.f;
}

__global__ void prep_kernel(const float* __restrict__ w10, const float* __restrict__ b10,
                            const float* __restrict__ w11) {
    int id = blockIdx.x * blockDim.x + threadIdx.x;
    // W1f: 16 pos x 32 lanes
    if (id < 16 * 32) {
        int pos = id >> 5, lane = id & 31;
        int n = pos >> 1, k = pos & 1;
        int g = lane >> 2, t = lane & 3;
        int j = n * 8 + g;
        float v0 = w1eff(w10, b10, k * 8 + t, j);
        float v1 = w1eff(w10, b10, k * 8 + t + 4, j);
        unsigned h0, l0, h1, l1;
        tf32_split(v0, h0, l0);
        tf32_split(v1, h1, l1);
        g_W1f[id] = make_uint4(h0, h1, l0, l1);
    }
    // W2f: 64 pos x 32 lanes
    int id2 = id - 16 * 32;
    if (id2 >= 0 && id2 < 64 * 32) {
        int pos = id2 >> 5, lane = id2 & 31;
        int n = pos >> 3, k = pos & 7;
        int g = lane >> 2, t = lane & 3;
        int j = n * 8 + g;
        float v0 = w11[(k * 8 + t) * 64 + j];
        float v1 = w11[(k * 8 + t + 4) * 64 + j];
        unsigned h0, l0, h1, l1;
        tf32_split(v0, h0, l0);
        tf32_split(v1, h1, l1);
        g_W2f[pos * 32 + lane] = make_uint4(h0, h1, l0, l1);
    }
}

// ---------------- sorting pipeline (once per launch) ----------------
__global__ void zero_hist_kernel() {
    int i = blockIdx.x * blockDim.x + threadIdx.x;
    if (i < N_NODES) g_hist[i] = 0;
}
__global__ void hist_kernel(const int* __restrict__ eidx) {
    int i = blockIdx.x * blockDim.x + threadIdx.x;
    if (i < N_EDGES) atomicAdd(&g_hist[eidx[N_EDGES + i]], 1);
}
__global__ void scan_kernel() {
    __shared__ int swarp[16];
    __shared__ int srun;
    int tid = threadIdx.x, lane = tid & 31, wid = tid >> 5;
    if (tid == 0) srun = 0;
    __syncthreads();
    const int CH = (N_NODES + 511) / 512;
    for (int c = 0; c < CH; c++) {
        int i = c * 512 + tid;
        int orig = (i < N_NODES) ? g_hist[i] : 0;
        int v = orig;
#pragma unroll
        for (int off = 1; off < 32; off <<= 1) {
            int n = __shfl_up_sync(FULLM, v, off);
            if (lane >= off) v += n;
        }
        if (lane == 31) swarp[wid] = v;
        __syncthreads();
        if (wid == 0) {
            int w = (lane < 16) ? swarp[lane] : 0;
#pragma unroll
            for (int off = 1; off < 16; off <<= 1) {
                int n = __shfl_up_sync(FULLM, w, off);
                if (lane >= off) w += n;
            }
            if (lane < 16) swarp[lane] = w;
        }
        __syncthreads();
        int base = (wid > 0) ? swarp[wid - 1] : 0;
        int incl = v + base;
        int run = srun;
        int excl = run + incl - orig;
        if (i < N_NODES) { g_rowptr[i] = excl; g_offs[i] = excl; }
        __syncthreads();
        if (tid == 511) srun = run + incl;
        __syncthreads();
    }
    if (threadIdx.x == 0) g_rowptr[N_NODES] = N_EDGES;
}
__global__ void scatter_kernel(const float* __restrict__ ea, const int* __restrict__ eidx) {
    int i = blockIdx.x * blockDim.x + threadIdx.x;
    if (i >= N_EDGES) return;
    int d = eidx[N_EDGES + i];
    int pos = atomicAdd(&g_offs[d], 1);
    g_srcs[pos] = eidx[i];
    g_dsts[pos] = d;
    const float* a = ea + (long long)i * 5;
    float* o = g_eas + (long long)pos * 8;
    o[0] = a[0]; o[1] = a[1]; o[2] = a[2]; o[3] = a[3]; o[4] = a[4];
}

// ---------------- fused iteration kernel (tensor-core edge MLP) ----------------
__global__ __launch_bounds__(TPB)
void fused_kernel(const float* __restrict__ x, float* __restrict__ y,
                  const float* __restrict__ b11,
                  const float* __restrict__ w20, const float* __restrict__ b20,
                  const float* __restrict__ w21, const float* __restrict__ b21) {
    extern __shared__ __align__(16) float dyn[];
    uint4* sW1f = reinterpret_cast<uint4*>(dyn + DYN_W1F);
    uint4* sW2f = reinterpret_cast<uint4*>(dyn + DYN_W2F);

    __shared__ float sW3[72 * 32];
    __shared__ float sb20[32];
    __shared__ float sW4[32 * 5];
    __shared__ float sb21[8];
    __shared__ int   saccum[NPB * H1];
    __shared__ float sxn[NPB * F_IN];
    __shared__ float sh2[NPB * 32];
    __shared__ float so[NPB * 5];
    __shared__ int   sdst[TPB];

    int tid = threadIdx.x;
    int w = tid >> 5;
    int lane = tid & 31;
    int g = lane >> 2;   // fragment group id (0..7)
    int t = lane & 3;    // thread id in group (0..3)

    // load fragment weights into smem
    {
        const uint4* gw1 = g_W1f;
        const uint4* gw2 = g_W2f;
        for (int i = tid; i < 16 * 32; i += TPB) sW1f[i] = gw1[i];
        for (int i = tid; i < 64 * 32; i += TPB) sW2f[i] = gw2[i];
    }
    for (int i = tid; i < 72 * 32; i += TPB) sW3[i] = w20[i];
    for (int i = tid; i < 32 * 5; i += TPB) sW4[i] = w21[i];
    if (tid < 32) sb20[tid] = b20[tid];
    if (tid < 5)  sb21[tid] = b21[tid];
    for (int i = tid; i < NPB * H1; i += TPB) saccum[i] = 0;
    int nodeBase = blockIdx.x * NPB;
    if (tid < NPB * F_IN) sxn[tid] = x[nodeBase * F_IN + tid];

    // GEMM2 bias C-init values for this thread's output columns
    float bj0[8], bj1[8];
#pragma unroll
    for (int n = 0; n < 8; n++) {
        bj0[n] = b11[n * 8 + 2 * t];
        bj1[n] = b11[n * 8 + 2 * t + 1];
    }
    __syncthreads();

    float* scr = dyn + DYN_SCR + w * SCR_SZ;   // warp-private scratch

    const int e0 = g_rowptr[nodeBase];
    const int e1 = g_rowptr[nodeBase + NPB];

    for (int eb = e0; eb < e1; eb += TPB) {
        // ---- staging: each thread stages its own edge (warp-local rows) ----
        {
            int e = eb + tid;
            bool act = e < e1;
            int r = lane;                      // row in this warp's 32-row region
            float tv[16];
#pragma unroll
            for (int k = 0; k < 16; k++) tv[k] = 0.f;
            int d = 255;
            if (act) {
                int src = g_srcs[e];
                d = g_dsts[e] - nodeBase;
                const float4* xr = reinterpret_cast<const float4*>(x + (long long)src * F_IN);
                float4 xa = __ldg(xr);
                float4 xb = __ldg(xr + 1);
                const float* a = g_eas + (long long)e * 8;
                float4 a4 = *reinterpret_cast<const float4*>(a);
                tv[0] = xa.x; tv[1] = xa.y; tv[2] = xa.z; tv[3] = xa.w;
                tv[4] = xb.x; tv[5] = xb.y; tv[6] = xb.z; tv[7] = xb.w;
                tv[8] = a4.x; tv[9] = a4.y; tv[10] = a4.z; tv[11] = a4.w;
                tv[12] = a[4];
                tv[13] = 1.f;   // bias slot for GEMM1
            }
            sdst[tid] = d;
            float* ar = scr + SCR_A1 + r * A1_STRIDE;
#pragma unroll
            for (int k = 0; k < 16; k++) ar[k] = tv[k];
        }
        __syncwarp();

        // ---- GEMM1: 2 tiles of 16 edges, K=16 (2 k-steps), N=64 ----
        // preload + split A fragments
        unsigned a1hi[2][2][4], a1lo[2][2][4];
#pragma unroll
        for (int tile = 0; tile < 2; tile++) {
#pragma unroll
            for (int k = 0; k < 2; k++) {
                const float* A = scr + SCR_A1 + (tile * 16) * A1_STRIDE;
                float f0 = A[g * A1_STRIDE + k * 8 + t];
                float f1 = A[(g + 8) * A1_STRIDE + k * 8 + t];
                float f2 = A[g * A1_STRIDE + k * 8 + t + 4];
                float f3 = A[(g + 8) * A1_STRIDE + k * 8 + t + 4];
                tf32_split(f0, a1hi[tile][k][0], a1lo[tile][k][0]);
                tf32_split(f1, a1hi[tile][k][1], a1lo[tile][k][1]);
                tf32_split(f2, a1hi[tile][k][2], a1lo[tile][k][2]);
                tf32_split(f3, a1hi[tile][k][3], a1lo[tile][k][3]);
            }
        }
#pragma unroll
        for (int n = 0; n < 8; n++) {
            float c[2][4];
#pragma unroll
            for (int tile = 0; tile < 2; tile++)
#pragma unroll
                for (int q = 0; q < 4; q++) c[tile][q] = 0.f;
#pragma unroll
            for (int k = 0; k < 2; k++) {
                uint4 B = sW1f[(n * 2 + k) * 32 + lane];
#pragma unroll
                for (int tile = 0; tile < 2; tile++) {
                    mma_tf32(c[tile][0], c[tile][1], c[tile][2], c[tile][3],
                             a1hi[tile][k][0], a1hi[tile][k][1], a1hi[tile][k][2], a1hi[tile][k][3],
                             B.x, B.y);
                    mma_tf32(c[tile][0], c[tile][1], c[tile][2], c[tile][3],
                             a1lo[tile][k][0], a1lo[tile][k][1], a1lo[tile][k][2], a1lo[tile][k][3],
                             B.x, B.y);
                    mma_tf32(c[tile][0], c[tile][1], c[tile][2], c[tile][3],
                             a1hi[tile][k][0], a1hi[tile][k][1], a1hi[tile][k][2], a1hi[tile][k][3],
                             B.z, B.w);
                }
            }
            // relu + store h tile
#pragma unroll
            for (int tile = 0; tile < 2; tile++) {
                float* H = scr + SCR_H + (tile * 16) * H_STRIDE;
                float2* p0 = reinterpret_cast<float2*>(H + g * H_STRIDE + n * 8 + 2 * t);
                float2* p1 = reinterpret_cast<float2*>(H + (g + 8) * H_STRIDE + n * 8 + 2 * t);
                *p0 = make_float2(fmaxf(c[tile][0], 0.f), fmaxf(c[tile][1], 0.f));
                *p1 = make_float2(fmaxf(c[tile][2], 0.f), fmaxf(c[tile][3], 0.f));
            }
        }
        __syncwarp();

        // ---- GEMM2: M=2x16 edges, K=64 (8 k-steps), N=64 ----
        float C2[2][8][4];
#pragma unroll
        for (int tile = 0; tile < 2; tile++)
#pragma unroll
            for (int n = 0; n < 8; n++) {
                C2[tile][n][0] = bj0[n];
                C2[tile][n][1] = bj1[n];
                C2[tile][n][2] = bj0[n];
                C2[tile][n][3] = bj1[n];
            }
#pragma unroll
        for (int k = 0; k < 8; k++) {
            unsigned ahi[2][4], alo[2][4];
#pragma unroll
            for (int tile = 0; tile < 2; tile++) {
                const float* H = scr + SCR_H + (tile * 16) * H_STRIDE;
                float f0 = H[g * H_STRIDE + k * 8 + t];
                float f1 = H[(g + 8) * H_STRIDE + k * 8 + t];
                float f2 = H[g * H_STRIDE + k * 8 + t + 4];
                float f3 = H[(g + 8) * H_STRIDE + k * 8 + t + 4];
                tf32_split(f0, ahi[tile][0], alo[tile][0]);
                tf32_split(f1, ahi[tile][1], alo[tile][1]);
                tf32_split(f2, ahi[tile][2], alo[tile][2]);
                tf32_split(f3, ahi[tile][3], alo[tile][3]);
            }
#pragma unroll
            for (int n = 0; n < 8; n++) {
                uint4 B = sW2f[(n * 8 + k) * 32 + lane];
#pragma unroll
                for (int tile = 0; tile < 2; tile++) {
                    mma_tf32(C2[tile][n][0], C2[tile][n][1], C2[tile][n][2], C2[tile][n][3],
                             ahi[tile][0], ahi[tile][1], ahi[tile][2], ahi[tile][3], B.x, B.y);
                    mma_tf32(C2[tile][n][0], C2[tile][n][1], C2[tile][n][2], C2[tile][n][3],
                             alo[tile][0], alo[tile][1], alo[tile][2], alo[tile][3], B.x, B.y);
                    mma_tf32(C2[tile][n][0], C2[tile][n][1], C2[tile][n][2], C2[tile][n][3],
                             ahi[tile][0], ahi[tile][1], ahi[tile][2], ahi[tile][3], B.z, B.w);
                }
            }
        }
        __syncwarp();   // h reads done; msg overlays scratch

        // ---- write msg tile (relu) ----
#pragma unroll
        for (int tile = 0; tile < 2; tile++) {
#pragma unroll
            for (int n = 0; n < 8; n++) {
                float* M = scr + (tile * 16) * MSG_STRIDE;
                float2* p0 = reinterpret_cast<float2*>(M + g * MSG_STRIDE + n * 8 + 2 * t);
                float2* p1 = reinterpret_cast<float2*>(M + (g + 8) * MSG_STRIDE + n * 8 + 2 * t);
                *p0 = make_float2(fmaxf(C2[tile][n][0], 0.f), fmaxf(C2[tile][n][1], 0.f));
                *p1 = make_float2(fmaxf(C2[tile][n][2], 0.f), fmaxf(C2[tile][n][3], 0.f));
            }
        }
        __syncwarp();

        // ---- segmented max over sorted rows; lane handles cols 2*lane, 2*lane+1 ----
        {
            int cur = 255;
            float mx0 = 0.f, mx1 = 0.f;
#pragma unroll 4
            for (int r = 0; r < 32; r++) {
                int d = sdst[w * 32 + r];
                if (d != cur) {
                    if (cur < NPB) {
                        atomicMax(&saccum[cur * H1 + 2 * lane], __float_as_int(mx0));
                        atomicMax(&saccum[cur * H1 + 2 * lane + 1], __float_as_int(mx1));
                    }
                    cur = d;
                    mx0 = 0.f; mx1 = 0.f;
                }
                if (d < NPB) {
                    float2 v = *reinterpret_cast<const float2*>(scr + r * MSG_STRIDE + 2 * lane);
                    mx0 = fmaxf(mx0, v.x);
                    mx1 = fmaxf(mx1, v.y);
                }
            }
            if (cur < NPB) {
                atomicMax(&saccum[cur * H1 + 2 * lane], __float_as_int(mx0));
                atomicMax(&saccum[cur * H1 + 2 * lane + 1], __float_as_int(mx1));
            }
        }
        __syncwarp();   // before next chunk's staging overwrites scratch
    }
    __syncthreads();

    // ---- node MLP for the block's 8 nodes ----
    {
        int s = tid >> 5, j = tid & 31;
        float acc = sb20[j];
#pragma unroll
        for (int k = 0; k < F_IN; k++)
            acc += sxn[s * F_IN + k] * sW3[k * 32 + j];
#pragma unroll 8
        for (int k = 0; k < H1; k++)
            acc += __int_as_float(saccum[s * H1 + k]) * sW3[(F_IN + k) * 32 + j];
        sh2[s * 32 + j] = fmaxf(acc, 0.f);
    }
    __syncthreads();
    if (tid < NPB * 5) {
        int s = tid / 5, jo = tid % 5;
        float acc = sb21[jo];
#pragma unroll
        for (int k = 0; k < 32; k++)
            acc += sh2[s * 32 + k] * sW4[k * 5 + jo];
        so[tid] = acc;
    }
    __syncthreads();
    if (tid < NPB) {
        int n = nodeBase + tid;
        float l  = so[tid * 5 + 0];
        float c1 = so[tid * 5 + 1];
        float c2 = so[tid * 5 + 2];
        float c3 = so[tid * 5 + 3];
        float c4 = so[tid * 5 + 4];
        float nor = sqrtf(c1 * c1 + c2 * c2 + c3 * c3 + c4 * c4);
        float dd = fmaxf(1.f, nor);
        float* yr = y + (long long)n * F_IN;
        yr[0] = l;
        yr[1] = c1 / dd;
        yr[2] = c2 / dd;
        yr[3] = c3 / dd;
        yr[4] = c4 / dd;
        yr[5] = sxn[tid * F_IN + 0];
        yr[6] = sxn[tid * F_IN + 1];
        yr[7] = sxn[tid * F_IN + 2];
    }
}

// ---------------- host ----------------
extern "C" void kernel_launch(void* const* d_in, const int* in_sizes, int n_in,
                              void* d_out, int out_size) {
    const float* x_in = (const float*)d_in[0];
    const float* ea   = (const float*)d_in[1];
    const int*   ei   = (const int*)d_in[2];
    const float* w10  = (const float*)d_in[3];
    const float* b10  = (const float*)d_in[4];
    const float* w11  = (const float*)d_in[5];
    const float* b11  = (const float*)d_in[6];
    const float* w20  = (const float*)d_in[7];
    const float* b20  = (const float*)d_in[8];
    const float* w21  = (const float*)d_in[9];
    const float* b21  = (const float*)d_in[10];

    float* xb[2];
    cudaGetSymbolAddress((void**)&xb[0], g_x0);
    cudaGetSymbolAddress((void**)&xb[1], g_x1);

    const int dyn_bytes = DYN_FLOATS * sizeof(float);   // 128 KB
    cudaFuncSetAttribute(fused_kernel, cudaFuncAttributeMaxDynamicSharedMemorySize, dyn_bytes);

    prep_kernel<<<16, 256>>>(w10, b10, w11);
    zero_hist_kernel<<<(N_NODES + 255) / 256, 256>>>();
    hist_kernel<<<(N_EDGES + 255) / 256, 256>>>(ei);
    scan_kernel<<<1, 512>>>();
    scatter_kernel<<<(N_EDGES + 255) / 256, 256>>>(ea, ei);

    const float* xin = x_in;
    for (int it = 0; it < N_ITERS; it++) {
        float* yout = (it == N_ITERS - 1) ? (float*)d_out : xb[it & 1];
        fused_kernel<<<NBLK, TPB, dyn_bytes>>>(xin, yout, b11, w20, b20, w21, b21);
        xin = yout;
    }
}

// round 8
// speedup vs baseline: 2.3173x; 1.3081x over previous
#include <cuda_runtime.h>
#include <math.h>

// Fixed problem shapes
#define N_NODES 50000
#define N_EDGES 3200000
#define F_IN    8      // 4*NT
#define H1      64
#define NPB     8      // nodes per block
#define NBLK    (N_NODES / NPB)   // 6250
#define TPB     256
#define N_ITERS 8
#define FULLM   0xffffffffu

// dynamic smem layout in uints:
//   W1F [0,1024): 8 n-pos x 32 lanes x uint4
//   W2F [1024,5120): 32 (n,kk)-pos x 32 lanes x uint4
//   per-warp scratch @5120, 3072 uints each:
//     A1H [0,384): 32 rows x stride 12 (8 bf16x2 pairs used)
//     A1L [384,768)
//     HH  [768,1920): 32 rows x stride 36 (32 pairs used)
//     HL  [1920,3072)
//     msg tile (floats, 32 x 66) overlays [0,2112) after GEMM2
#define DYN_W1F  0
#define DYN_W2F  1024
#define DYN_SCR  5120
#define SCR_A1H  0
#define SCR_A1L  384
#define SCR_HH   768
#define SCR_HL   1920
#define SCR_SZ   3072
#define A1_STR   12
#define H_STR    36
#define MSG_STRIDE 66
#define DYN_UINTS (5120 + 8 * SCR_SZ)   // 29696 uints = 118784 B

// ---------------- device scratch ----------------
__device__ float g_x0[N_NODES * F_IN];
__device__ float g_x1[N_NODES * F_IN];
__device__ int   g_hist[N_NODES];
__device__ int   g_rowptr[N_NODES + 1];
__device__ int   g_offs[N_NODES];
__device__ int   g_srcs[N_EDGES];
__device__ int   g_dsts[N_EDGES];
__device__ float g_eas[(long long)N_EDGES * 8];

// fragment-ordered bf16-split weights: uint4 = {Bh0, Bh1, Bl0, Bl1}
__device__ uint4 g_W1f[8 * 32];    // pos = n           (K=16, 1 k-step)
__device__ uint4 g_W2f[32 * 32];   // pos = n*4 + kk    (K=64, 4 k-steps)

// ---------------- bf16 helpers ----------------
// pack two floats to bf16x2: first operand -> UPPER half, second -> LOWER half
__device__ __forceinline__ unsigned bf2_pack(float up, float lo) {
    unsigned d;
    asm("cvt.rn.bf16x2.f32 %0, %1, %2;" : "=r"(d) : "f"(up), "f"(lo));
    return d;
}
// split pair (x0 = lower element, x1 = upper element) into hi/lo bf16x2 words
__device__ __forceinline__ void bf2_split(float x0, float x1, unsigned& h2, unsigned& l2) {
    h2 = bf2_pack(x1, x0);
    float fh0 = __uint_as_float(h2 << 16);
    float fh1 = __uint_as_float(h2 & 0xffff0000u);
    l2 = bf2_pack(x1 - fh1, x0 - fh0);
}
__device__ __forceinline__ void mma_bf16(float& c0, float& c1, float& c2, float& c3,
                                         unsigned a0, unsigned a1, unsigned a2, unsigned a3,
                                         unsigned b0, unsigned b1) {
    asm("mma.sync.aligned.m16n8k16.row.col.f32.bf16.bf16.f32 "
        "{%0,%1,%2,%3}, {%4,%5,%6,%7}, {%8,%9}, {%0,%1,%2,%3};"
        : "+f"(c0), "+f"(c1), "+f"(c2), "+f"(c3)
        : "r"(a0), "r"(a1), "r"(a2), "r"(a3), "r"(b0), "r"(b1));
}

// ---------------- weight fragment preparation ----------------
__device__ __forceinline__ float w1eff(const float* w10, const float* b10, int k, int j) {
    if (k < 13) return w10[k * 64 + j];
    if (k == 13) return b10[j];
    return 0.f;
}

__global__ void prep_kernel(const float* __restrict__ w10, const float* __restrict__ b10,
                            const float* __restrict__ w11) {
    int id = blockIdx.x * blockDim.x + threadIdx.x;
    // W1f: 8 pos x 32 lanes   (B fragment for m16n8k16, col-major k16 x n8)
    if (id < 8 * 32) {
        int n = id >> 5, lane = id & 31;
        int g = lane >> 2, t = lane & 3;
        int j = n * 8 + g;
        float v0 = w1eff(w10, b10, 2 * t, j);
        float v1 = w1eff(w10, b10, 2 * t + 1, j);
        float v2 = w1eff(w10, b10, 2 * t + 8, j);
        float v3 = w1eff(w10, b10, 2 * t + 9, j);
        unsigned h01, l01, h23, l23;
        bf2_split(v0, v1, h01, l01);
        bf2_split(v2, v3, h23, l23);
        g_W1f[id] = make_uint4(h01, h23, l01, l23);
    }
    // W2f: 32 pos x 32 lanes
    int id2 = id - 8 * 32;
    if (id2 >= 0 && id2 < 32 * 32) {
        int pos = id2 >> 5, lane = id2 & 31;
        int n = pos >> 2, kk = pos & 3;
        int g = lane >> 2, t = lane & 3;
        int j = n * 8 + g;
        int kb = kk * 16;
        float v0 = w11[(kb + 2 * t) * 64 + j];
        float v1 = w11[(kb + 2 * t + 1) * 64 + j];
        float v2 = w11[(kb + 2 * t + 8) * 64 + j];
        float v3 = w11[(kb + 2 * t + 9) * 64 + j];
        unsigned h01, l01, h23, l23;
        bf2_split(v0, v1, h01, l01);
        bf2_split(v2, v3, h23, l23);
        g_W2f[pos * 32 + lane] = make_uint4(h01, h23, l01, l23);
    }
}

// ---------------- sorting pipeline (once per launch) ----------------
__global__ void zero_hist_kernel() {
    int i = blockIdx.x * blockDim.x + threadIdx.x;
    if (i < N_NODES) g_hist[i] = 0;
}
__global__ void hist_kernel(const int* __restrict__ eidx) {
    int i = blockIdx.x * blockDim.x + threadIdx.x;
    if (i < N_EDGES) atomicAdd(&g_hist[eidx[N_EDGES + i]], 1);
}
__global__ void scan_kernel() {
    __shared__ int swarp[16];
    __shared__ int srun;
    int tid = threadIdx.x, lane = tid & 31, wid = tid >> 5;
    if (tid == 0) srun = 0;
    __syncthreads();
    const int CH = (N_NODES + 511) / 512;
    for (int c = 0; c < CH; c++) {
        int i = c * 512 + tid;
        int orig = (i < N_NODES) ? g_hist[i] : 0;
        int v = orig;
#pragma unroll
        for (int off = 1; off < 32; off <<= 1) {
            int n = __shfl_up_sync(FULLM, v, off);
            if (lane >= off) v += n;
        }
        if (lane == 31) swarp[wid] = v;
        __syncthreads();
        if (wid == 0) {
            int w = (lane < 16) ? swarp[lane] : 0;
#pragma unroll
            for (int off = 1; off < 16; off <<= 1) {
                int n = __shfl_up_sync(FULLM, w, off);
                if (lane >= off) w += n;
            }
            if (lane < 16) swarp[lane] = w;
        }
        __syncthreads();
        int base = (wid > 0) ? swarp[wid - 1] : 0;
        int incl = v + base;
        int run = srun;
        int excl = run + incl - orig;
        if (i < N_NODES) { g_rowptr[i] = excl; g_offs[i] = excl; }
        __syncthreads();
        if (tid == 511) srun = run + incl;
        __syncthreads();
    }
    if (threadIdx.x == 0) g_rowptr[N_NODES] = N_EDGES;
}
__global__ void scatter_kernel(const float* __restrict__ ea, const int* __restrict__ eidx) {
    int i = blockIdx.x * blockDim.x + threadIdx.x;
    if (i >= N_EDGES) return;
    int d = eidx[N_EDGES + i];
    int pos = atomicAdd(&g_offs[d], 1);
    g_srcs[pos] = eidx[i];
    g_dsts[pos] = d;
    const float* a = ea + (long long)i * 5;
    float* o = g_eas + (long long)pos * 8;
    o[0] = a[0]; o[1] = a[1]; o[2] = a[2]; o[3] = a[3]; o[4] = a[4];
}

// ---------------- fused iteration kernel (bf16-split tensor-core edge MLP) ----------------
__global__ __launch_bounds__(TPB)
void fused_kernel(const float* __restrict__ x, float* __restrict__ y,
                  const float* __restrict__ b11,
                  const float* __restrict__ w20, const float* __restrict__ b20,
                  const float* __restrict__ w21, const float* __restrict__ b21) {
    extern __shared__ __align__(16) unsigned dynu[];
    uint4* sW1f = reinterpret_cast<uint4*>(dynu + DYN_W1F);
    uint4* sW2f = reinterpret_cast<uint4*>(dynu + DYN_W2F);

    __shared__ float sW3[72 * 32];
    __shared__ float sb20[32];
    __shared__ float sW4[32 * 5];
    __shared__ float sb21[8];
    __shared__ int   saccum[NPB * H1];
    __shared__ float sxn[NPB * F_IN];
    __shared__ float sh2[NPB * 32];
    __shared__ float so[NPB * 5];
    __shared__ int   sdst[TPB];

    int tid = threadIdx.x;
    int w = tid >> 5;
    int lane = tid & 31;
    int g = lane >> 2;   // fragment group id (0..7)
    int t = lane & 3;    // thread id in group (0..3)

    {
        const uint4* gw1 = g_W1f;
        const uint4* gw2 = g_W2f;
        for (int i = tid; i < 8 * 32; i += TPB) sW1f[i] = gw1[i];
        for (int i = tid; i < 32 * 32; i += TPB) sW2f[i] = gw2[i];
    }
    for (int i = tid; i < 72 * 32; i += TPB) sW3[i] = w20[i];
    for (int i = tid; i < 32 * 5; i += TPB) sW4[i] = w21[i];
    if (tid < 32) sb20[tid] = b20[tid];
    if (tid < 5)  sb21[tid] = b21[tid];
    for (int i = tid; i < NPB * H1; i += TPB) saccum[i] = 0;
    int nodeBase = blockIdx.x * NPB;
    if (tid < NPB * F_IN) sxn[tid] = x[nodeBase * F_IN + tid];

    // GEMM2 bias C-init for this thread's output columns
    float bj0[8], bj1[8];
#pragma unroll
    for (int n = 0; n < 8; n++) {
        bj0[n] = b11[n * 8 + 2 * t];
        bj1[n] = b11[n * 8 + 2 * t + 1];
    }
    __syncthreads();

    unsigned* scr = dynu + DYN_SCR + w * SCR_SZ;   // warp-private scratch
    unsigned* A1H = scr + SCR_A1H;
    unsigned* A1L = scr + SCR_A1L;
    unsigned* HH  = scr + SCR_HH;
    unsigned* HL  = scr + SCR_HL;
    float* scrf   = reinterpret_cast<float*>(scr);  // msg overlay

    const int e0 = g_rowptr[nodeBase];
    const int e1 = g_rowptr[nodeBase + NPB];

    for (int eb = e0; eb < e1; eb += TPB) {
        // ---- staging: each thread stages one edge, split to bf16 hi/lo planes ----
        {
            int e = eb + tid;
            bool act = e < e1;
            int r = lane;
            float tv[16];
#pragma unroll
            for (int k = 0; k < 16; k++) tv[k] = 0.f;
            int d = 255;
            if (act) {
                int src = g_srcs[e];
                d = g_dsts[e] - nodeBase;
                const float4* xr = reinterpret_cast<const float4*>(x + (long long)src * F_IN);
                float4 xa = __ldg(xr);
                float4 xb = __ldg(xr + 1);
                const float* a = g_eas + (long long)e * 8;
                float4 a4 = *reinterpret_cast<const float4*>(a);
                tv[0] = xa.x; tv[1] = xa.y; tv[2] = xa.z; tv[3] = xa.w;
                tv[4] = xb.x; tv[5] = xb.y; tv[6] = xb.z; tv[7] = xb.w;
                tv[8] = a4.x; tv[9] = a4.y; tv[10] = a4.z; tv[11] = a4.w;
                tv[12] = a[4];
                tv[13] = 1.f;   // bias slot
            }
            sdst[tid] = d;
            unsigned hh[8], ll[8];
#pragma unroll
            for (int p = 0; p < 8; p++)
                bf2_split(tv[2 * p], tv[2 * p + 1], hh[p], ll[p]);
            uint4* ph = reinterpret_cast<uint4*>(A1H + r * A1_STR);
            uint4* pl = reinterpret_cast<uint4*>(A1L + r * A1_STR);
            ph[0] = make_uint4(hh[0], hh[1], hh[2], hh[3]);
            ph[1] = make_uint4(hh[4], hh[5], hh[6], hh[7]);
            pl[0] = make_uint4(ll[0], ll[1], ll[2], ll[3]);
            pl[1] = make_uint4(ll[4], ll[5], ll[6], ll[7]);
        }
        __syncwarp();

        // ---- GEMM1: 2 tiles of 16 edges, K=16 (1 k-step), N=64, 3 passes ----
        {
            unsigned ah[2][4], al[2][4];
#pragma unroll
            for (int tile = 0; tile < 2; tile++) {
                int rb = tile * 16;
                ah[tile][0] = A1H[(rb + g) * A1_STR + t];
                ah[tile][1] = A1H[(rb + g + 8) * A1_STR + t];
                ah[tile][2] = A1H[(rb + g) * A1_STR + t + 4];
                ah[tile][3] = A1H[(rb + g + 8) * A1_STR + t + 4];
                al[tile][0] = A1L[(rb + g) * A1_STR + t];
                al[tile][1] = A1L[(rb + g + 8) * A1_STR + t];
                al[tile][2] = A1L[(rb + g) * A1_STR + t + 4];
                al[tile][3] = A1L[(rb + g + 8) * A1_STR + t + 4];
            }
#pragma unroll
            for (int n = 0; n < 8; n++) {
                uint4 B = sW1f[n * 32 + lane];
                float c[2][4];
#pragma unroll
                for (int tile = 0; tile < 2; tile++) {
                    c[tile][0] = 0.f; c[tile][1] = 0.f; c[tile][2] = 0.f; c[tile][3] = 0.f;
                    mma_bf16(c[tile][0], c[tile][1], c[tile][2], c[tile][3],
                             ah[tile][0], ah[tile][1], ah[tile][2], ah[tile][3], B.x, B.y);
                    mma_bf16(c[tile][0], c[tile][1], c[tile][2], c[tile][3],
                             al[tile][0], al[tile][1], al[tile][2], al[tile][3], B.x, B.y);
                    mma_bf16(c[tile][0], c[tile][1], c[tile][2], c[tile][3],
                             ah[tile][0], ah[tile][1], ah[tile][2], ah[tile][3], B.z, B.w);
                    // relu + split-once + store h pairs to hi/lo planes
                    int rb = tile * 16;
                    float r0 = fmaxf(c[tile][0], 0.f);
                    float r1 = fmaxf(c[tile][1], 0.f);
                    float r2 = fmaxf(c[tile][2], 0.f);
                    float r3 = fmaxf(c[tile][3], 0.f);
                    unsigned h01, l01, h23, l23;
                    bf2_split(r0, r1, h01, l01);
                    bf2_split(r2, r3, h23, l23);
                    int p = n * 4 + t;
                    HH[(rb + g) * H_STR + p] = h01;
                    HL[(rb + g) * H_STR + p] = l01;
                    HH[(rb + g + 8) * H_STR + p] = h23;
                    HL[(rb + g + 8) * H_STR + p] = l23;
                }
            }
        }
        __syncwarp();

        // ---- GEMM2: M=2x16 edges, K=64 (4 k-steps), N=64, 3 passes ----
        float C2[2][8][4];
#pragma unroll
        for (int tile = 0; tile < 2; tile++)
#pragma unroll
            for (int n = 0; n < 8; n++) {
                C2[tile][n][0] = bj0[n];
                C2[tile][n][1] = bj1[n];
                C2[tile][n][2] = bj0[n];
                C2[tile][n][3] = bj1[n];
            }
#pragma unroll
        for (int kk = 0; kk < 4; kk++) {
            unsigned ah[2][4], al[2][4];
#pragma unroll
            for (int tile = 0; tile < 2; tile++) {
                int rb = tile * 16;
                int b0 = (rb + g) * H_STR + kk * 8;
                int b1 = (rb + g + 8) * H_STR + kk * 8;
                ah[tile][0] = HH[b0 + t];
                ah[tile][1] = HH[b1 + t];
                ah[tile][2] = HH[b0 + t + 4];
                ah[tile][3] = HH[b1 + t + 4];
                al[tile][0] = HL[b0 + t];
                al[tile][1] = HL[b1 + t];
                al[tile][2] = HL[b0 + t + 4];
                al[tile][3] = HL[b1 + t + 4];
            }
#pragma unroll
            for (int n = 0; n < 8; n++) {
                uint4 B = sW2f[(n * 4 + kk) * 32 + lane];
#pragma unroll
                for (int tile = 0; tile < 2; tile++) {
                    mma_bf16(C2[tile][n][0], C2[tile][n][1], C2[tile][n][2], C2[tile][n][3],
                             ah[tile][0], ah[tile][1], ah[tile][2], ah[tile][3], B.x, B.y);
                    mma_bf16(C2[tile][n][0], C2[tile][n][1], C2[tile][n][2], C2[tile][n][3],
                             al[tile][0], al[tile][1], al[tile][2], al[tile][3], B.x, B.y);
                    mma_bf16(C2[tile][n][0], C2[tile][n][1], C2[tile][n][2], C2[tile][n][3],
                             ah[tile][0], ah[tile][1], ah[tile][2], ah[tile][3], B.z, B.w);
                }
            }
        }
        __syncwarp();   // all plane reads done; msg overlays scratch

        // ---- write msg tile (relu) ----
#pragma unroll
        for (int tile = 0; tile < 2; tile++) {
#pragma unroll
            for (int n = 0; n < 8; n++) {
                float* M = scrf + (tile * 16) * MSG_STRIDE;
                float2* p0 = reinterpret_cast<float2*>(M + g * MSG_STRIDE + n * 8 + 2 * t);
                float2* p1 = reinterpret_cast<float2*>(M + (g + 8) * MSG_STRIDE + n * 8 + 2 * t);
                *p0 = make_float2(fmaxf(C2[tile][n][0], 0.f), fmaxf(C2[tile][n][1], 0.f));
                *p1 = make_float2(fmaxf(C2[tile][n][2], 0.f), fmaxf(C2[tile][n][3], 0.f));
            }
        }
        __syncwarp();

        // ---- segmented max over sorted rows; lane handles cols 2*lane, 2*lane+1 ----
        {
            int cur = 255;
            float mx0 = 0.f, mx1 = 0.f;
#pragma unroll 4
            for (int r = 0; r < 32; r++) {
                int d = sdst[w * 32 + r];
                if (d != cur) {
                    if (cur < NPB) {
                        atomicMax(&saccum[cur * H1 + 2 * lane], __float_as_int(mx0));
                        atomicMax(&saccum[cur * H1 + 2 * lane + 1], __float_as_int(mx1));
                    }
                    cur = d;
                    mx0 = 0.f; mx1 = 0.f;
                }
                if (d < NPB) {
                    float2 v = *reinterpret_cast<const float2*>(scrf + r * MSG_STRIDE + 2 * lane);
                    mx0 = fmaxf(mx0, v.x);
                    mx1 = fmaxf(mx1, v.y);
                }
            }
            if (cur < NPB) {
                atomicMax(&saccum[cur * H1 + 2 * lane], __float_as_int(mx0));
                atomicMax(&saccum[cur * H1 + 2 * lane + 1], __float_as_int(mx1));
            }
        }
        __syncwarp();   // before next chunk's staging overwrites scratch
    }
    __syncthreads();

    // ---- node MLP for the block's 8 nodes ----
    {
        int s = tid >> 5, j = tid & 31;
        float acc = sb20[j];
#pragma unroll
        for (int k = 0; k < F_IN; k++)
            acc += sxn[s * F_IN + k] * sW3[k * 32 + j];
#pragma unroll 8
        for (int k = 0; k < H1; k++)
            acc += __int_as_float(saccum[s * H1 + k]) * sW3[(F_IN + k) * 32 + j];
        sh2[s * 32 + j] = fmaxf(acc, 0.f);
    }
    __syncthreads();
    if (tid < NPB * 5) {
        int s = tid / 5, jo = tid % 5;
        float acc = sb21[jo];
#pragma unroll
        for (int k = 0; k < 32; k++)
            acc += sh2[s * 32 + k] * sW4[k * 5 + jo];
        so[tid] = acc;
    }
    __syncthreads();
    if (tid < NPB) {
        int n = nodeBase + tid;
        float l  = so[tid * 5 + 0];
        float c1 = so[tid * 5 + 1];
        float c2 = so[tid * 5 + 2];
        float c3 = so[tid * 5 + 3];
        float c4 = so[tid * 5 + 4];
        float nor = sqrtf(c1 * c1 + c2 * c2 + c3 * c3 + c4 * c4);
        float dd = fmaxf(1.f, nor);
        float* yr = y + (long long)n * F_IN;
        yr[0] = l;
        yr[1] = c1 / dd;
        yr[2] = c2 / dd;
        yr[3] = c3 / dd;
        yr[4] = c4 / dd;
        yr[5] = sxn[tid * F_IN + 0];
        yr[6] = sxn[tid * F_IN + 1];
        yr[7] = sxn[tid * F_IN + 2];
    }
}

// ---------------- host ----------------
extern "C" void kernel_launch(void* const* d_in, const int* in_sizes, int n_in,
                              void* d_out, int out_size) {
    const float* x_in = (const float*)d_in[0];
    const float* ea   = (const float*)d_in[1];
    const int*   ei   = (const int*)d_in[2];
    const float* w10  = (const float*)d_in[3];
    const float* b10  = (const float*)d_in[4];
    const float* w11  = (const float*)d_in[5];
    const float* b11  = (const float*)d_in[6];
    const float* w20  = (const float*)d_in[7];
    const float* b20  = (const float*)d_in[8];
    const float* w21  = (const float*)d_in[9];
    const float* b21  = (const float*)d_in[10];

    float* xb[2];
    cudaGetSymbolAddress((void**)&xb[0], g_x0);
    cudaGetSymbolAddress((void**)&xb[1], g_x1);

    const int dyn_bytes = DYN_UINTS * sizeof(unsigned);   // ~116 KB
    cudaFuncSetAttribute(fused_kernel, cudaFuncAttributeMaxDynamicSharedMemorySize, dyn_bytes);

    prep_kernel<<<16, 256>>>(w10, b10, w11);
    zero_hist_kernel<<<(N_NODES + 255) / 256, 256>>>();
    hist_kernel<<<(N_EDGES + 255) / 256, 256>>>(ei);
    scan_kernel<<<1, 512>>>();
    scatter_kernel<<<(N_EDGES + 255) / 256, 256>>>(ea, ei);

    const float* xin = x_in;
    for (int it = 0; it < N_ITERS; it++) {
        float* yout = (it == N_ITERS - 1) ? (float*)d_out : xb[it & 1];
        fused_kernel<<<NBLK, TPB, dyn_bytes>>>(xin, yout, b11, w20, b20, w21, b21);
        xin = yout;
    }
}

// round 9
// speedup vs baseline: 3.4637x; 1.4947x over previous
#include <cuda_runtime.h>
#include <math.h>

// Fixed problem shapes
#define N_NODES 50000
#define N_EDGES 3200000
#define F_IN    8      // 4*NT
#define H1      64
#define NPB     8      // nodes per block
#define NBLK    (N_NODES / NPB)   // 6250
#define TPB     256
#define N_ITERS 8
#define FULLM   0xffffffffu

// dynamic smem layout in uints:
//   W1F [0,1024): 8 n-pos x 32 lanes x uint4
//   W2F [1024,5120): 32 (n,kk)-pos x 32 lanes x uint4
//   per-warp scratch @5120, 1824 uints each:
//     A1H [0,384): 32 rows x stride 12 (8 bf16x2 pairs used)
//     A1L [384,768)
//     MSG [768,1824): 16 rows x 66 floats (per-tile msg)
#define DYN_W1F  0
#define DYN_W2F  1024
#define DYN_SCR  5120
#define SCR_A1H  0
#define SCR_A1L  384
#define SCR_MSG  768
#define SCR_SZ   1824
#define A1_STR   12
#define MSG_STRIDE 66
#define DYN_UINTS (5120 + 8 * SCR_SZ)   // 19712 uints = 78848 B

// ---------------- device scratch ----------------
__device__ float g_x0[N_NODES * F_IN];
__device__ float g_x1[N_NODES * F_IN];
__device__ int   g_hist[N_NODES];
__device__ int   g_rowptr[N_NODES + 1];
__device__ int   g_offs[N_NODES];
__device__ int   g_srcs[N_EDGES];
__device__ int   g_dsts[N_EDGES];
__device__ float g_eas[(long long)N_EDGES * 8];

// fragment-ordered bf16-split weights: uint4 = {Bh0, Bh1, Bl0, Bl1}
__device__ uint4 g_W1f[8 * 32];    // pos = n           (K=16, 1 k-step)
__device__ uint4 g_W2f[32 * 32];   // pos = n*4 + kk    (K=64, 4 k-steps)

// ---------------- bf16 helpers ----------------
__device__ __forceinline__ unsigned bf2_pack(float up, float lo) {
    unsigned d;
    asm("cvt.rn.bf16x2.f32 %0, %1, %2;" : "=r"(d) : "f"(up), "f"(lo));
    return d;
}
// split pair (x0 = lower element, x1 = upper element) into hi/lo bf16x2 words
__device__ __forceinline__ void bf2_split(float x0, float x1, unsigned& h2, unsigned& l2) {
    h2 = bf2_pack(x1, x0);
    float fh0 = __uint_as_float(h2 << 16);
    float fh1 = __uint_as_float(h2 & 0xffff0000u);
    l2 = bf2_pack(x1 - fh1, x0 - fh0);
}
__device__ __forceinline__ void mma_bf16(float& c0, float& c1, float& c2, float& c3,
                                         unsigned a0, unsigned a1, unsigned a2, unsigned a3,
                                         unsigned b0, unsigned b1) {
    asm("mma.sync.aligned.m16n8k16.row.col.f32.bf16.bf16.f32 "
        "{%0,%1,%2,%3}, {%4,%5,%6,%7}, {%8,%9}, {%0,%1,%2,%3};"
        : "+f"(c0), "+f"(c1), "+f"(c2), "+f"(c3)
        : "r"(a0), "r"(a1), "r"(a2), "r"(a3), "r"(b0), "r"(b1));
}

// ---------------- weight fragment preparation ----------------
__device__ __forceinline__ float w1eff(const float* w10, const float* b10, int k, int j) {
    if (k < 13) return w10[k * 64 + j];
    if (k == 13) return b10[j];
    return 0.f;
}

__global__ void prep_kernel(const float* __restrict__ w10, const float* __restrict__ b10,
                            const float* __restrict__ w11) {
    int id = blockIdx.x * blockDim.x + threadIdx.x;
    if (id < 8 * 32) {
        int n = id >> 5, lane = id & 31;
        int g = lane >> 2, t = lane & 3;
        int j = n * 8 + g;
        float v0 = w1eff(w10, b10, 2 * t, j);
        float v1 = w1eff(w10, b10, 2 * t + 1, j);
        float v2 = w1eff(w10, b10, 2 * t + 8, j);
        float v3 = w1eff(w10, b10, 2 * t + 9, j);
        unsigned h01, l01, h23, l23;
        bf2_split(v0, v1, h01, l01);
        bf2_split(v2, v3, h23, l23);
        g_W1f[id] = make_uint4(h01, h23, l01, l23);
    }
    int id2 = id - 8 * 32;
    if (id2 >= 0 && id2 < 32 * 32) {
        int pos = id2 >> 5, lane = id2 & 31;
        int n = pos >> 2, kk = pos & 3;
        int g = lane >> 2, t = lane & 3;
        int j = n * 8 + g;
        int kb = kk * 16;
        float v0 = w11[(kb + 2 * t) * 64 + j];
        float v1 = w11[(kb + 2 * t + 1) * 64 + j];
        float v2 = w11[(kb + 2 * t + 8) * 64 + j];
        float v3 = w11[(kb + 2 * t + 9) * 64 + j];
        unsigned h01, l01, h23, l23;
        bf2_split(v0, v1, h01, l01);
        bf2_split(v2, v3, h23, l23);
        g_W2f[pos * 32 + lane] = make_uint4(h01, h23, l01, l23);
    }
}

// ---------------- sorting pipeline (once per launch) ----------------
__global__ void zero_hist_kernel() {
    int i = blockIdx.x * blockDim.x + threadIdx.x;
    if (i < N_NODES) g_hist[i] = 0;
}
__global__ void hist_kernel(const int* __restrict__ eidx) {
    int i = blockIdx.x * blockDim.x + threadIdx.x;
    if (i < N_EDGES) atomicAdd(&g_hist[eidx[N_EDGES + i]], 1);
}
__global__ void scan_kernel() {
    __shared__ int swarp[16];
    __shared__ int srun;
    int tid = threadIdx.x, lane = tid & 31, wid = tid >> 5;
    if (tid == 0) srun = 0;
    __syncthreads();
    const int CH = (N_NODES + 511) / 512;
    for (int c = 0; c < CH; c++) {
        int i = c * 512 + tid;
        int orig = (i < N_NODES) ? g_hist[i] : 0;
        int v = orig;
#pragma unroll
        for (int off = 1; off < 32; off <<= 1) {
            int n = __shfl_up_sync(FULLM, v, off);
            if (lane >= off) v += n;
        }
        if (lane == 31) swarp[wid] = v;
        __syncthreads();
        if (wid == 0) {
            int w = (lane < 16) ? swarp[lane] : 0;
#pragma unroll
            for (int off = 1; off < 16; off <<= 1) {
                int n = __shfl_up_sync(FULLM, w, off);
                if (lane >= off) w += n;
            }
            if (lane < 16) swarp[lane] = w;
        }
        __syncthreads();
        int base = (wid > 0) ? swarp[wid - 1] : 0;
        int incl = v + base;
        int run = srun;
        int excl = run + incl - orig;
        if (i < N_NODES) { g_rowptr[i] = excl; g_offs[i] = excl; }
        __syncthreads();
        if (tid == 511) srun = run + incl;
        __syncthreads();
    }
    if (threadIdx.x == 0) g_rowptr[N_NODES] = N_EDGES;
}
__global__ void scatter_kernel(const float* __restrict__ ea, const int* __restrict__ eidx) {
    int i = blockIdx.x * blockDim.x + threadIdx.x;
    if (i >= N_EDGES) return;
    int d = eidx[N_EDGES + i];
    int pos = atomicAdd(&g_offs[d], 1);
    g_srcs[pos] = eidx[i];
    g_dsts[pos] = d;
    const float* a = ea + (long long)i * 5;
    float* o = g_eas + (long long)pos * 8;
    o[0] = a[0]; o[1] = a[1]; o[2] = a[2]; o[3] = a[3]; o[4] = a[4];
}

// ---------------- fused iteration kernel ----------------
// bf16-split tensor-core edge MLP with in-register GEMM1-C -> GEMM2-A repack.
__global__ __launch_bounds__(TPB, 2)
void fused_kernel(const float* __restrict__ x, float* __restrict__ y,
                  const float* __restrict__ b11,
                  const float* __restrict__ w20, const float* __restrict__ b20,
                  const float* __restrict__ w21, const float* __restrict__ b21) {
    extern __shared__ __align__(16) unsigned dynu[];
    uint4* sW1f = reinterpret_cast<uint4*>(dynu + DYN_W1F);
    uint4* sW2f = reinterpret_cast<uint4*>(dynu + DYN_W2F);

    __shared__ float sW3[72 * 32];
    __shared__ float sb20[32];
    __shared__ float sW4[32 * 5];
    __shared__ float sb21[8];
    __shared__ int   saccum[NPB * H1];
    __shared__ float sxn[NPB * F_IN];
    __shared__ float sh2[NPB * 32];
    __shared__ float so[NPB * 5];
    __shared__ int   sdst[TPB];

    int tid = threadIdx.x;
    int w = tid >> 5;
    int lane = tid & 31;
    int g = lane >> 2;   // fragment group id (0..7)
    int t = lane & 3;    // thread id in group (0..3)

    {
        const uint4* gw1 = g_W1f;
        const uint4* gw2 = g_W2f;
        for (int i = tid; i < 8 * 32; i += TPB) sW1f[i] = gw1[i];
        for (int i = tid; i < 32 * 32; i += TPB) sW2f[i] = gw2[i];
    }
    for (int i = tid; i < 72 * 32; i += TPB) sW3[i] = w20[i];
    for (int i = tid; i < 32 * 5; i += TPB) sW4[i] = w21[i];
    if (tid < 32) sb20[tid] = b20[tid];
    if (tid < 5)  sb21[tid] = b21[tid];
    for (int i = tid; i < NPB * H1; i += TPB) saccum[i] = 0;
    int nodeBase = blockIdx.x * NPB;
    if (tid < NPB * F_IN) sxn[tid] = x[nodeBase * F_IN + tid];

    // GEMM2 bias C-init for this thread's output columns
    float bj0[8], bj1[8];
#pragma unroll
    for (int n = 0; n < 8; n++) {
        bj0[n] = b11[n * 8 + 2 * t];
        bj1[n] = b11[n * 8 + 2 * t + 1];
    }
    __syncthreads();

    unsigned* scr = dynu + DYN_SCR + w * SCR_SZ;
    unsigned* A1H = scr + SCR_A1H;
    unsigned* A1L = scr + SCR_A1L;
    float* MSG    = reinterpret_cast<float*>(scr + SCR_MSG);

    const int e0 = g_rowptr[nodeBase];
    const int e1 = g_rowptr[nodeBase + NPB];

    for (int eb = e0; eb < e1; eb += TPB) {
        // ---- staging: each thread stages one edge, split to bf16 hi/lo planes ----
        {
            int e = eb + tid;
            bool act = e < e1;
            int r = lane;
            float tv[16];
#pragma unroll
            for (int k = 0; k < 16; k++) tv[k] = 0.f;
            int d = 255;
            if (act) {
                int src = g_srcs[e];
                d = g_dsts[e] - nodeBase;
                const float4* xr = reinterpret_cast<const float4*>(x + (long long)src * F_IN);
                float4 xa = __ldg(xr);
                float4 xb = __ldg(xr + 1);
                const float* a = g_eas + (long long)e * 8;
                float4 a4 = *reinterpret_cast<const float4*>(a);
                tv[0] = xa.x; tv[1] = xa.y; tv[2] = xa.z; tv[3] = xa.w;
                tv[4] = xb.x; tv[5] = xb.y; tv[6] = xb.z; tv[7] = xb.w;
                tv[8] = a4.x; tv[9] = a4.y; tv[10] = a4.z; tv[11] = a4.w;
                tv[12] = a[4];
                tv[13] = 1.f;   // bias slot
            }
            sdst[tid] = d;
            unsigned hh[8], ll[8];
#pragma unroll
            for (int p = 0; p < 8; p++)
                bf2_split(tv[2 * p], tv[2 * p + 1], hh[p], ll[p]);
            uint4* ph = reinterpret_cast<uint4*>(A1H + r * A1_STR);
            uint4* pl = reinterpret_cast<uint4*>(A1L + r * A1_STR);
            ph[0] = make_uint4(hh[0], hh[1], hh[2], hh[3]);
            ph[1] = make_uint4(hh[4], hh[5], hh[6], hh[7]);
            pl[0] = make_uint4(ll[0], ll[1], ll[2], ll[3]);
            pl[1] = make_uint4(ll[4], ll[5], ll[6], ll[7]);
        }
        __syncwarp();

        // ---- process two 16-edge tiles sequentially ----
#pragma unroll 1
        for (int tile = 0; tile < 2; tile++) {
            int rb = tile * 16;

            // GEMM1 A fragments from staged planes
            unsigned ah0 = A1H[(rb + g) * A1_STR + t];
            unsigned ah1 = A1H[(rb + g + 8) * A1_STR + t];
            unsigned ah2 = A1H[(rb + g) * A1_STR + t + 4];
            unsigned ah3 = A1H[(rb + g + 8) * A1_STR + t + 4];
            unsigned al0 = A1L[(rb + g) * A1_STR + t];
            unsigned al1 = A1L[(rb + g + 8) * A1_STR + t];
            unsigned al2 = A1L[(rb + g) * A1_STR + t + 4];
            unsigned al3 = A1L[(rb + g + 8) * A1_STR + t + 4];

            // GEMM1 -> relu -> in-register split into GEMM2 A-fragments
            // hA[n][0] = pack(rows g : c0,c1), hA[n][1] = pack(rows g+8 : c2,c3)
            unsigned hA[8][2], lA[8][2];
#pragma unroll
            for (int n = 0; n < 8; n++) {
                uint4 B = sW1f[n * 32 + lane];
                float c0 = 0.f, c1 = 0.f, c2 = 0.f, c3 = 0.f;
                mma_bf16(c0, c1, c2, c3, ah0, ah1, ah2, ah3, B.x, B.y);
                mma_bf16(c0, c1, c2, c3, al0, al1, al2, al3, B.x, B.y);
                mma_bf16(c0, c1, c2, c3, ah0, ah1, ah2, ah3, B.z, B.w);
                c0 = fmaxf(c0, 0.f); c1 = fmaxf(c1, 0.f);
                c2 = fmaxf(c2, 0.f); c3 = fmaxf(c3, 0.f);
                bf2_split(c0, c1, hA[n][0], lA[n][0]);
                bf2_split(c2, c3, hA[n][1], lA[n][1]);
            }

            // GEMM2: K=64 (4 k-steps), A-fragments straight from registers
            float C2[8][4];
#pragma unroll
            for (int n = 0; n < 8; n++) {
                C2[n][0] = bj0[n]; C2[n][1] = bj1[n];
                C2[n][2] = bj0[n]; C2[n][3] = bj1[n];
            }
#pragma unroll
            for (int kk = 0; kk < 4; kk++) {
                unsigned a0h = hA[2 * kk][0],     a1h = hA[2 * kk][1];
                unsigned a2h = hA[2 * kk + 1][0], a3h = hA[2 * kk + 1][1];
                unsigned a0l = lA[2 * kk][0],     a1l = lA[2 * kk][1];
                unsigned a2l = lA[2 * kk + 1][0], a3l = lA[2 * kk + 1][1];
#pragma unroll
                for (int n = 0; n < 8; n++) {
                    uint4 B = sW2f[(n * 4 + kk) * 32 + lane];
                    mma_bf16(C2[n][0], C2[n][1], C2[n][2], C2[n][3],
                             a0h, a1h, a2h, a3h, B.x, B.y);
                    mma_bf16(C2[n][0], C2[n][1], C2[n][2], C2[n][3],
                             a0l, a1l, a2l, a3l, B.x, B.y);
                    mma_bf16(C2[n][0], C2[n][1], C2[n][2], C2[n][3],
                             a0h, a1h, a2h, a3h, B.z, B.w);
                }
            }

            // msg tile (16 rows) with relu
#pragma unroll
            for (int n = 0; n < 8; n++) {
                float2* p0 = reinterpret_cast<float2*>(MSG + g * MSG_STRIDE + n * 8 + 2 * t);
                float2* p1 = reinterpret_cast<float2*>(MSG + (g + 8) * MSG_STRIDE + n * 8 + 2 * t);
                *p0 = make_float2(fmaxf(C2[n][0], 0.f), fmaxf(C2[n][1], 0.f));
                *p1 = make_float2(fmaxf(C2[n][2], 0.f), fmaxf(C2[n][3], 0.f));
            }
            __syncwarp();

            // segmented max over the 16 sorted rows; lane owns cols 2*lane, 2*lane+1
            {
                int cur = 255;
                float mx0 = 0.f, mx1 = 0.f;
#pragma unroll 4
                for (int r = 0; r < 16; r++) {
                    int d = sdst[w * 32 + rb + r];
                    if (d != cur) {
                        if (cur < NPB) {
                            atomicMax(&saccum[cur * H1 + 2 * lane], __float_as_int(mx0));
                            atomicMax(&saccum[cur * H1 + 2 * lane + 1], __float_as_int(mx1));
                        }
                        cur = d;
                        mx0 = 0.f; mx1 = 0.f;
                    }
                    if (d < NPB) {
                        float2 v = *reinterpret_cast<const float2*>(MSG + r * MSG_STRIDE + 2 * lane);
                        mx0 = fmaxf(mx0, v.x);
                        mx1 = fmaxf(mx1, v.y);
                    }
                }
                if (cur < NPB) {
                    atomicMax(&saccum[cur * H1 + 2 * lane], __float_as_int(mx0));
                    atomicMax(&saccum[cur * H1 + 2 * lane + 1], __float_as_int(mx1));
                }
            }
            __syncwarp();   // before next tile / next chunk reuses MSG & A1
        }
    }
    __syncthreads();

    // ---- node MLP for the block's 8 nodes ----
    {
        int s = tid >> 5, j = tid & 31;
        float acc = sb20[j];
#pragma unroll
        for (int k = 0; k < F_IN; k++)
            acc += sxn[s * F_IN + k] * sW3[k * 32 + j];
#pragma unroll 8
        for (int k = 0; k < H1; k++)
            acc += __int_as_float(saccum[s * H1 + k]) * sW3[(F_IN + k) * 32 + j];
        sh2[s * 32 + j] = fmaxf(acc, 0.f);
    }
    __syncthreads();
    if (tid < NPB * 5) {
        int s = tid / 5, jo = tid % 5;
        float acc = sb21[jo];
#pragma unroll
        for (int k = 0; k < 32; k++)
            acc += sh2[s * 32 + k] * sW4[k * 5 + jo];
        so[tid] = acc;
    }
    __syncthreads();
    if (tid < NPB) {
        int n = nodeBase + tid;
        float l  = so[tid * 5 + 0];
        float c1 = so[tid * 5 + 1];
        float c2 = so[tid * 5 + 2];
        float c3 = so[tid * 5 + 3];
        float c4 = so[tid * 5 + 4];
        float nor = sqrtf(c1 * c1 + c2 * c2 + c3 * c3 + c4 * c4);
        float dd = fmaxf(1.f, nor);
        float* yr = y + (long long)n * F_IN;
        yr[0] = l;
        yr[1] = c1 / dd;
        yr[2] = c2 / dd;
        yr[3] = c3 / dd;
        yr[4] = c4 / dd;
        yr[5] = sxn[tid * F_IN + 0];
        yr[6] = sxn[tid * F_IN + 1];
        yr[7] = sxn[tid * F_IN + 2];
    }
}

// ---------------- host ----------------
extern "C" void kernel_launch(void* const* d_in, const int* in_sizes, int n_in,
                              void* d_out, int out_size) {
    const float* x_in = (const float*)d_in[0];
    const float* ea   = (const float*)d_in[1];
    const int*   ei   = (const int*)d_in[2];
    const float* w10  = (const float*)d_in[3];
    const float* b10  = (const float*)d_in[4];
    const float* w11  = (const float*)d_in[5];
    const float* b11  = (const float*)d_in[6];
    const float* w20  = (const float*)d_in[7];
    const float* b20  = (const float*)d_in[8];
    const float* w21  = (const float*)d_in[9];
    const float* b21  = (const float*)d_in[10];

    float* xb[2];
    cudaGetSymbolAddress((void**)&xb[0], g_x0);
    cudaGetSymbolAddress((void**)&xb[1], g_x1);

    const int dyn_bytes = DYN_UINTS * sizeof(unsigned);   // ~77 KB
    cudaFuncSetAttribute(fused_kernel, cudaFuncAttributeMaxDynamicSharedMemorySize, dyn_bytes);

    prep_kernel<<<16, 256>>>(w10, b10, w11);
    zero_hist_kernel<<<(N_NODES + 255) / 256, 256>>>();
    hist_kernel<<<(N_EDGES + 255) / 256, 256>>>(ei);
    scan_kernel<<<1, 512>>>();
    scatter_kernel<<<(N_EDGES + 255) / 256, 256>>>(ea, ei);

    const float* xin = x_in;
    for (int it = 0; it < N_ITERS; it++) {
        float* yout = (it == N_ITERS - 1) ? (float*)d_out : xb[it & 1];
        fused_kernel<<<NBLK, TPB, dyn_bytes>>>(xin, yout, b11, w20, b20, w21, b21);
        xin = yout;
    }
}

// round 12
// speedup vs baseline: 3.6495x; 1.0537x over previous
#include <cuda_runtime.h>
#include <cuda_fp16.h>
#include <math.h>

// Fixed problem shapes
#define N_NODES 50000
#define N_EDGES 3200000
#define F_IN    8      // 4*NT
#define H1      64
#define NPB     8      // nodes per block
#define NBLK    (N_NODES / NPB)   // 6250
#define TPB     256
#define N_ITERS 8
#define FULLM   0xffffffffu

// dynamic smem layout in uints:
//   W1F [0,1024): 8 n-pos x 32 lanes x uint4   {Ah-pass B pairs: h01,h23, lo-pass: l01,l23}
//   W2F [1024,5120): 32 (n,kk)-pos x 32 lanes x uint4  {bh01,bh23, bl01,bl23}
//   per-warp scratch @5120, 1824 uints each:
//     A1H [0,384): 32 rows x stride 12 (8 fp16x2 pairs used)
//     A1L [384,768)
//     MSG [768,1824): 16 rows x 66 floats (per-tile msg)
#define DYN_W1F  0
#define DYN_W2F  1024
#define DYN_SCR  5120
#define SCR_A1H  0
#define SCR_A1L  384
#define SCR_MSG  768
#define SCR_SZ   1824
#define A1_STR   12
#define MSG_STRIDE 66
#define DYN_UINTS (5120 + 8 * SCR_SZ)   // 19712 uints = 78848 B

// ---------------- device scratch ----------------
__device__ float g_x0[N_NODES * F_IN];
__device__ float g_x1[N_NODES * F_IN];
__device__ int   g_hist[N_NODES];
__device__ int   g_rowptr[N_NODES + 1];
__device__ int   g_offs[N_NODES];
__device__ int   g_srcs[N_EDGES];
__device__ int   g_dsts[N_EDGES];
__device__ float g_eas[(long long)N_EDGES * 8];

// fragment-ordered fp16-split weights
__device__ uint4 g_W1f[8 * 32];    // pos = n           (K=16, 1 k-step)
__device__ uint4 g_W2f[32 * 32];   // pos = n*4 + kk    (K=64, 4 k-steps)

// ---------------- fp16 helpers ----------------
__device__ __forceinline__ unsigned f16_pack(float up, float lo) {
    unsigned d;
    asm("cvt.rn.f16x2.f32 %0, %1, %2;" : "=r"(d) : "f"(up), "f"(lo));
    return d;
}
// split pair (x0 = lower element, x1 = upper element) into hi/lo fp16x2 words
__device__ __forceinline__ void f16_split(float x0, float x1, unsigned& h2, unsigned& l2) {
    h2 = f16_pack(x1, x0);
    __half2 hv = *reinterpret_cast<__half2*>(&h2);
    float2 f = __half22float2(hv);   // f.x = lower(x0h), f.y = upper(x1h)
    l2 = f16_pack(x1 - f.y, x0 - f.x);
}
__device__ __forceinline__ void mma_f16(float& c0, float& c1, float& c2, float& c3,
                                        unsigned a0, unsigned a1, unsigned a2, unsigned a3,
                                        unsigned b0, unsigned b1) {
    asm("mma.sync.aligned.m16n8k16.row.col.f32.f16.f16.f32 "
        "{%0,%1,%2,%3}, {%4,%5,%6,%7}, {%8,%9}, {%0,%1,%2,%3};"
        : "+f"(c0), "+f"(c1), "+f"(c2), "+f"(c3)
        : "r"(a0), "r"(a1), "r"(a2), "r"(a3), "r"(b0), "r"(b1));
}

// ---------------- weight fragment preparation (+ hist zero, fused) ----------------
__device__ __forceinline__ float w1eff(const float* w10, const float* b10, int k, int j) {
    if (k < 13) return w10[k * 64 + j];
    if (k == 13) return b10[j];
    return 0.f;
}

__global__ void prep_kernel(const float* __restrict__ w10, const float* __restrict__ b10,
                            const float* __restrict__ w11) {
    int id = blockIdx.x * blockDim.x + threadIdx.x;
    // zero the histogram (grid-stride) — fused here to reduce pre-launch count
    for (int i = id; i < N_NODES; i += gridDim.x * blockDim.x) g_hist[i] = 0;

    if (id < 8 * 32) {
        int n = id >> 5, lane = id & 31;
        int g = lane >> 2, t = lane & 3;
        int j = n * 8 + g;
        float v0 = w1eff(w10, b10, 2 * t, j);
        float v1 = w1eff(w10, b10, 2 * t + 1, j);
        float v2 = w1eff(w10, b10, 2 * t + 8, j);
        float v3 = w1eff(w10, b10, 2 * t + 9, j);
        unsigned h01, l01, h23, l23;
        f16_split(v0, v1, h01, l01);
        f16_split(v2, v3, h23, l23);
        g_W1f[id] = make_uint4(h01, h23, l01, l23);
    }
    int id2 = id - 8 * 32;
    if (id2 >= 0 && id2 < 32 * 32) {
        int pos = id2 >> 5, lane = id2 & 31;
        int n = pos >> 2, kk = pos & 3;
        int g = lane >> 2, t = lane & 3;
        int j = n * 8 + g;
        int kb = kk * 16;
        float v0 = w11[(kb + 2 * t) * 64 + j];
        float v1 = w11[(kb + 2 * t + 1) * 64 + j];
        float v2 = w11[(kb + 2 * t + 8) * 64 + j];
        float v3 = w11[(kb + 2 * t + 9) * 64 + j];
        unsigned h01, l01, h23, l23;
        f16_split(v0, v1, h01, l01);
        f16_split(v2, v3, h23, l23);
        g_W2f[pos * 32 + lane] = make_uint4(h01, h23, l01, l23);
    }
}

// ---------------- sorting pipeline (once per launch) ----------------
__global__ void hist_kernel(const int* __restrict__ eidx) {
    int i = blockIdx.x * blockDim.x + threadIdx.x;
    if (i < N_EDGES) atomicAdd(&g_hist[eidx[N_EDGES + i]], 1);
}
__global__ void scan_kernel() {
    __shared__ int swarp[16];
    __shared__ int srun;
    int tid = threadIdx.x, lane = tid & 31, wid = tid >> 5;
    if (tid == 0) srun = 0;
    __syncthreads();
    const int CH = (N_NODES + 511) / 512;
    for (int c = 0; c < CH; c++) {
        int i = c * 512 + tid;
        int orig = (i < N_NODES) ? g_hist[i] : 0;
        int v = orig;
#pragma unroll
        for (int off = 1; off < 32; off <<= 1) {
            int n = __shfl_up_sync(FULLM, v, off);
            if (lane >= off) v += n;
        }
        if (lane == 31) swarp[wid] = v;
        __syncthreads();
        if (wid == 0) {
            int w = (lane < 16) ? swarp[lane] : 0;
#pragma unroll
            for (int off = 1; off < 16; off <<= 1) {
                int n = __shfl_up_sync(FULLM, w, off);
                if (lane >= off) w += n;
            }
            if (lane < 16) swarp[lane] = w;
        }
        __syncthreads();
        int base = (wid > 0) ? swarp[wid - 1] : 0;
        int incl = v + base;
        int run = srun;
        int excl = run + incl - orig;
        if (i < N_NODES) { g_rowptr[i] = excl; g_offs[i] = excl; }
        __syncthreads();
        if (tid == 511) srun = run + incl;
        __syncthreads();
    }
    if (threadIdx.x == 0) g_rowptr[N_NODES] = N_EDGES;
}
__global__ void scatter_kernel(const float* __restrict__ ea, const int* __restrict__ eidx) {
    int i = blockIdx.x * blockDim.x + threadIdx.x;
    if (i >= N_EDGES) return;
    int d = eidx[N_EDGES + i];
    int pos = atomicAdd(&g_offs[d], 1);
    g_srcs[pos] = eidx[i];
    g_dsts[pos] = d;
    const float* a = ea + (long long)i * 5;
    float* o = g_eas + (long long)pos * 8;
    o[0] = a[0]; o[1] = a[1]; o[2] = a[2]; o[3] = a[3]; o[4] = a[4];
}

// ---------------- fused iteration kernel ----------------
// fp16-split tensor-core edge MLP. GEMM1: 3-pass. GEMM2: 2-pass (A = fp16(h) single plane).
__global__ __launch_bounds__(TPB, 2)
void fused_kernel(const float* __restrict__ x, float* __restrict__ y,
                  const float* __restrict__ b11,
                  const float* __restrict__ w20, const float* __restrict__ b20,
                  const float* __restrict__ w21, const float* __restrict__ b21) {
    extern __shared__ __align__(16) unsigned dynu[];
    uint4* sW1f = reinterpret_cast<uint4*>(dynu + DYN_W1F);
    uint4* sW2f = reinterpret_cast<uint4*>(dynu + DYN_W2F);

    __shared__ float sW3[72 * 32];
    __shared__ float sb20[32];
    __shared__ float sW4[32 * 5];
    __shared__ float sb21[8];
    __shared__ int   saccum[NPB * H1];
    __shared__ float sxn[NPB * F_IN];
    __shared__ float sh2[NPB * 32];
    __shared__ float so[NPB * 5];
    __shared__ int   sdst[TPB];

    int tid = threadIdx.x;
    int w = tid >> 5;
    int lane = tid & 31;
    int g = lane >> 2;   // fragment group id (0..7)
    int t = lane & 3;    // thread id in group (0..3)

    {
        const uint4* gw1 = g_W1f;
        const uint4* gw2 = g_W2f;
        for (int i = tid; i < 8 * 32; i += TPB) sW1f[i] = gw1[i];
        for (int i = tid; i < 32 * 32; i += TPB) sW2f[i] = gw2[i];
    }
    for (int i = tid; i < 72 * 32; i += TPB) sW3[i] = w20[i];
    for (int i = tid; i < 32 * 5; i += TPB) sW4[i] = w21[i];
    if (tid < 32) sb20[tid] = b20[tid];
    if (tid < 5)  sb21[tid] = b21[tid];
    for (int i = tid; i < NPB * H1; i += TPB) saccum[i] = 0;
    int nodeBase = blockIdx.x * NPB;
    if (tid < NPB * F_IN) sxn[tid] = x[nodeBase * F_IN + tid];

    // GEMM2 bias C-init for this thread's output columns
    float bj0[8], bj1[8];
#pragma unroll
    for (int n = 0; n < 8; n++) {
        bj0[n] = b11[n * 8 + 2 * t];
        bj1[n] = b11[n * 8 + 2 * t + 1];
    }
    __syncthreads();

    unsigned* scr = dynu + DYN_SCR + w * SCR_SZ;
    unsigned* A1H = scr + SCR_A1H;
    unsigned* A1L = scr + SCR_A1L;
    float* MSG    = reinterpret_cast<float*>(scr + SCR_MSG);

    const int e0 = g_rowptr[nodeBase];
    const int e1 = g_rowptr[nodeBase + NPB];

    for (int eb = e0; eb < e1; eb += TPB) {
        // ---- staging: each thread stages one edge, split to fp16 hi/lo planes ----
        {
            int e = eb + tid;
            bool act = e < e1;
            int r = lane;
            float tv[16];
#pragma unroll
            for (int k = 0; k < 16; k++) tv[k] = 0.f;
            int d = 255;
            if (act) {
                int src = g_srcs[e];
                d = g_dsts[e] - nodeBase;
                const float4* xr = reinterpret_cast<const float4*>(x + (long long)src * F_IN);
                float4 xa = __ldg(xr);
                float4 xb = __ldg(xr + 1);
                const float* a = g_eas + (long long)e * 8;
                float4 a4 = *reinterpret_cast<const float4*>(a);
                tv[0] = xa.x; tv[1] = xa.y; tv[2] = xa.z; tv[3] = xa.w;
                tv[4] = xb.x; tv[5] = xb.y; tv[6] = xb.z; tv[7] = xb.w;
                tv[8] = a4.x; tv[9] = a4.y; tv[10] = a4.z; tv[11] = a4.w;
                tv[12] = a[4];
                tv[13] = 1.f;   // bias slot
            }
            sdst[tid] = d;
            unsigned hh[8], ll[8];
#pragma unroll
            for (int p = 0; p < 8; p++)
                f16_split(tv[2 * p], tv[2 * p + 1], hh[p], ll[p]);
            uint4* ph = reinterpret_cast<uint4*>(A1H + r * A1_STR);
            uint4* pl = reinterpret_cast<uint4*>(A1L + r * A1_STR);
            ph[0] = make_uint4(hh[0], hh[1], hh[2], hh[3]);
            ph[1] = make_uint4(hh[4], hh[5], hh[6], hh[7]);
            pl[0] = make_uint4(ll[0], ll[1], ll[2], ll[3]);
            pl[1] = make_uint4(ll[4], ll[5], ll[6], ll[7]);
        }
        __syncwarp();

        // ---- process two 16-edge tiles sequentially ----
#pragma unroll 1
        for (int tile = 0; tile < 2; tile++) {
            int rb = tile * 16;

            // GEMM1 A fragments from staged planes
            unsigned ah0 = A1H[(rb + g) * A1_STR + t];
            unsigned ah1 = A1H[(rb + g + 8) * A1_STR + t];
            unsigned ah2 = A1H[(rb + g) * A1_STR + t + 4];
            unsigned ah3 = A1H[(rb + g + 8) * A1_STR + t + 4];
            unsigned al0 = A1L[(rb + g) * A1_STR + t];
            unsigned al1 = A1L[(rb + g + 8) * A1_STR + t];
            unsigned al2 = A1L[(rb + g) * A1_STR + t + 4];
            unsigned al3 = A1L[(rb + g + 8) * A1_STR + t + 4];

            // GEMM1 (3-pass) -> relu -> single-plane fp16 repack into GEMM2 A-fragments
            unsigned hA[8][2];
#pragma unroll
            for (int n = 0; n < 8; n++) {
                uint4 B = sW1f[n * 32 + lane];
                float c0 = 0.f, c1 = 0.f, c2 = 0.f, c3 = 0.f;
                mma_f16(c0, c1, c2, c3, ah0, ah1, ah2, ah3, B.x, B.y);
                mma_f16(c0, c1, c2, c3, al0, al1, al2, al3, B.x, B.y);
                mma_f16(c0, c1, c2, c3, ah0, ah1, ah2, ah3, B.z, B.w);
                c0 = fmaxf(c0, 0.f); c1 = fmaxf(c1, 0.f);
                c2 = fmaxf(c2, 0.f); c3 = fmaxf(c3, 0.f);
                hA[n][0] = f16_pack(c1, c0);
                hA[n][1] = f16_pack(c3, c2);
            }

            // GEMM2: K=64 (4 k-steps), 2 passes: fp16(h)*Bh + fp16(h)*Bl = fp16(h)*B
            float C2[8][4];
#pragma unroll
            for (int n = 0; n < 8; n++) {
                C2[n][0] = bj0[n]; C2[n][1] = bj1[n];
                C2[n][2] = bj0[n]; C2[n][3] = bj1[n];
            }
#pragma unroll
            for (int kk = 0; kk < 4; kk++) {
                unsigned a0 = hA[2 * kk][0],     a1 = hA[2 * kk][1];
                unsigned a2 = hA[2 * kk + 1][0], a3 = hA[2 * kk + 1][1];
#pragma unroll
                for (int n = 0; n < 8; n++) {
                    uint4 B = sW2f[(n * 4 + kk) * 32 + lane];
                    mma_f16(C2[n][0], C2[n][1], C2[n][2], C2[n][3],
                            a0, a1, a2, a3, B.x, B.y);
                    mma_f16(C2[n][0], C2[n][1], C2[n][2], C2[n][3],
                            a0, a1, a2, a3, B.z, B.w);
                }
            }

            // msg tile (16 rows) with relu
#pragma unroll
            for (int n = 0; n < 8; n++) {
                float2* p0 = reinterpret_cast<float2*>(MSG + g * MSG_STRIDE + n * 8 + 2 * t);
                float2* p1 = reinterpret_cast<float2*>(MSG + (g + 8) * MSG_STRIDE + n * 8 + 2 * t);
                *p0 = make_float2(fmaxf(C2[n][0], 0.f), fmaxf(C2[n][1], 0.f));
                *p1 = make_float2(fmaxf(C2[n][2], 0.f), fmaxf(C2[n][3], 0.f));
            }
            __syncwarp();

            // segmented max over the 16 sorted rows; lane owns cols 2*lane, 2*lane+1
            {
                int cur = 255;
                float mx0 = 0.f, mx1 = 0.f;
#pragma unroll 4
                for (int r = 0; r < 16; r++) {
                    int d = sdst[w * 32 + rb + r];
                    if (d != cur) {
                        if (cur < NPB) {
                            atomicMax(&saccum[cur * H1 + 2 * lane], __float_as_int(mx0));
                            atomicMax(&saccum[cur * H1 + 2 * lane + 1], __float_as_int(mx1));
                        }
                        cur = d;
                        mx0 = 0.f; mx1 = 0.f;
                    }
                    if (d < NPB) {
                        float2 v = *reinterpret_cast<const float2*>(MSG + r * MSG_STRIDE + 2 * lane);
                        mx0 = fmaxf(mx0, v.x);
                        mx1 = fmaxf(mx1, v.y);
                    }
                }
                if (cur < NPB) {
                    atomicMax(&saccum[cur * H1 + 2 * lane], __float_as_int(mx0));
                    atomicMax(&saccum[cur * H1 + 2 * lane + 1], __float_as_int(mx1));
                }
            }
            __syncwarp();   // before next tile / next chunk reuses MSG & A1
        }
    }
    __syncthreads();

    // ---- node MLP for the block's 8 nodes ----
    {
        int s = tid >> 5, j = tid & 31;
        float acc = sb20[j];
#pragma unroll
        for (int k = 0; k < F_IN; k++)
            acc += sxn[s * F_IN + k] * sW3[k * 32 + j];
#pragma unroll 8
        for (int k = 0; k < H1; k++)
            acc += __int_as_float(saccum[s * H1 + k]) * sW3[(F_IN + k) * 32 + j];
        sh2[s * 32 + j] = fmaxf(acc, 0.f);
    }
    __syncthreads();
    if (tid < NPB * 5) {
        int s = tid / 5, jo = tid % 5;
        float acc = sb21[jo];
#pragma unroll
        for (int k = 0; k < 32; k++)
            acc += sh2[s * 32 + k] * sW4[k * 5 + jo];
        so[tid] = acc;
    }
    __syncthreads();
    if (tid < NPB) {
        int n = nodeBase + tid;
        float l  = so[tid * 5 + 0];
        float c1 = so[tid * 5 + 1];
        float c2 = so[tid * 5 + 2];
        float c3 = so[tid * 5 + 3];
        float c4 = so[tid * 5 + 4];
        float nor = sqrtf(c1 * c1 + c2 * c2 + c3 * c3 + c4 * c4);
        float dd = fmaxf(1.f, nor);
        float* yr = y + (long long)n * F_IN;
        yr[0] = l;
        yr[1] = c1 / dd;
        yr[2] = c2 / dd;
        yr[3] = c3 / dd;
        yr[4] = c4 / dd;
        yr[5] = sxn[tid * F_IN + 0];
        yr[6] = sxn[tid * F_IN + 1];
        yr[7] = sxn[tid * F_IN + 2];
    }
}

// ---------------- host ----------------
extern "C" void kernel_launch(void* const* d_in, const int* in_sizes, int n_in,
                              void* d_out, int out_size) {
    const float* x_in = (const float*)d_in[0];
    const float* ea   = (const float*)d_in[1];
    const int*   ei   = (const int*)d_in[2];
    const float* w10  = (const float*)d_in[3];
    const float* b10  = (const float*)d_in[4];
    const float* w11  = (const float*)d_in[5];
    const float* b11  = (const float*)d_in[6];
    const float* w20  = (const float*)d_in[7];
    const float* b20  = (const float*)d_in[8];
    const float* w21  = (const float*)d_in[9];
    const float* b21  = (const float*)d_in[10];

    float* xb[2];
    cudaGetSymbolAddress((void**)&xb[0], g_x0);
    cudaGetSymbolAddress((void**)&xb[1], g_x1);

    const int dyn_bytes = DYN_UINTS * sizeof(unsigned);   // ~77 KB
    cudaFuncSetAttribute(fused_kernel, cudaFuncAttributeMaxDynamicSharedMemorySize, dyn_bytes);

    // 4 pre-launches so ncu (-s 5 -c 1) captures fused_kernel iteration #2
    prep_kernel<<<64, 256>>>(w10, b10, w11);
    hist_kernel<<<(N_EDGES + 255) / 256, 256>>>(ei);
    scan_kernel<<<1, 512>>>();
    scatter_kernel<<<(N_EDGES + 255) / 256, 256>>>(ea, ei);

    const float* xin = x_in;
    for (int it = 0; it < N_ITERS; it++) {
        float* yout = (it == N_ITERS - 1) ? (float*)d_out : xb[it & 1];
        fused_kernel<<<NBLK, TPB, dyn_bytes>>>(xin, yout, b11, w20, b20, w21, b21);
        xin = yout;
    }
}

// round 15
// speedup vs baseline: 4.0592x; 1.1123x over previous
#include <cuda_runtime.h>
#include <cuda_fp16.h>
#include <math.h>

// Fixed problem shapes
#define N_NODES 50000
#define N_EDGES 3200000
#define F_IN    8      // 4*NT
#define H1      64
#define NPB     8      // nodes per block
#define NBLK    (N_NODES / NPB)   // 6250
#define TPB     256
#define N_ITERS 8
#define FULLM   0xffffffffu

// dynamic smem layout in uints:
//   W1F [0,1024): 8 n-pos x 32 lanes x uint4   {Bh01,Bh23, Bl01,Bl23}
//   W2F [1024,5120): 32 (n,kk)-pos x 32 lanes x uint4
//   per-warp scratch @5120, 1440 uints each:
//     A1H [0,384): 32 rows x stride 12 (8 fp16x2 pairs used, single hi plane)
//     MSG [384,1440): 16 rows x 66 floats (per-tile msg)
#define DYN_W1F  0
#define DYN_W2F  1024
#define DYN_SCR  5120
#define SCR_A1H  0
#define SCR_MSG  384
#define SCR_SZ   1440
#define A1_STR   12
#define MSG_STRIDE 66
#define DYN_UINTS (5120 + 8 * SCR_SZ)   // 16640 uints = 66560 B

// ---------------- device scratch ----------------
__device__ float g_x0[N_NODES * F_IN];
__device__ float g_x1[N_NODES * F_IN];
__device__ uint4 g_xsA[N_NODES];        // fp16-pair image of node features (ping)
__device__ uint4 g_xsB[N_NODES];        // (pong)
__device__ int   g_hist[N_NODES];
__device__ int   g_rowptr[N_NODES + 1];
__device__ int   g_offs[N_NODES];
__device__ int   g_srcs[N_EDGES];
__device__ int   g_dsts[N_EDGES];
__device__ uint4 g_econst[N_EDGES];     // fp16 pairs: (a0,a1),(a2,a3),(a4,1.0),0

// fragment-ordered fp16-split weights (B side keeps 2 planes)
__device__ uint4 g_W1f[8 * 32];    // pos = n           (K=16, 1 k-step)
__device__ uint4 g_W2f[32 * 32];   // pos = n*4 + kk    (K=64, 4 k-steps)

// ---------------- fp16 helpers ----------------
__device__ __forceinline__ unsigned f16_pack(float up, float lo) {
    unsigned d;
    asm("cvt.rn.f16x2.f32 %0, %1, %2;" : "=r"(d) : "f"(up), "f"(lo));
    return d;
}
// split pair (x0 = lower element, x1 = upper element) into hi/lo fp16x2 words
__device__ __forceinline__ void f16_split(float x0, float x1, unsigned& h2, unsigned& l2) {
    h2 = f16_pack(x1, x0);
    __half2 hv = *reinterpret_cast<__half2*>(&h2);
    float2 f = __half22float2(hv);
    l2 = f16_pack(x1 - f.y, x0 - f.x);
}
__device__ __forceinline__ void mma_f16(float& c0, float& c1, float& c2, float& c3,
                                        unsigned a0, unsigned a1, unsigned a2, unsigned a3,
                                        unsigned b0, unsigned b1) {
    asm("mma.sync.aligned.m16n8k16.row.col.f32.f16.f16.f32 "
        "{%0,%1,%2,%3}, {%4,%5,%6,%7}, {%8,%9}, {%0,%1,%2,%3};"
        : "+f"(c0), "+f"(c1), "+f"(c2), "+f"(c3)
        : "r"(a0), "r"(a1), "r"(a2), "r"(a3), "r"(b0), "r"(b1));
}

// ---------------- prep: weight fragments + x fp16 image + histogram ----------------
// g_hist is zeroed by the END of the previous call's scatter_kernel (BSS-zero on
// first call), so the atomics here always see a clean histogram.
__device__ __forceinline__ float w1eff(const float* w10, const float* b10, int k, int j) {
    if (k < 13) return w10[k * 64 + j];
    if (k == 13) return b10[j];
    return 0.f;
}

__global__ void prep_kernel(const float* __restrict__ x,
                            const float* __restrict__ w10, const float* __restrict__ b10,
                            const float* __restrict__ w11,
                            const int* __restrict__ eidx) {
    int id = blockIdx.x * blockDim.x + threadIdx.x;
    int stride = gridDim.x * blockDim.x;

    if (id < 8 * 32) {
        int n = id >> 5, lane = id & 31;
        int g = lane >> 2, t = lane & 3;
        int j = n * 8 + g;
        float v0 = w1eff(w10, b10, 2 * t, j);
        float v1 = w1eff(w10, b10, 2 * t + 1, j);
        float v2 = w1eff(w10, b10, 2 * t + 8, j);
        float v3 = w1eff(w10, b10, 2 * t + 9, j);
        unsigned h01, l01, h23, l23;
        f16_split(v0, v1, h01, l01);
        f16_split(v2, v3, h23, l23);
        g_W1f[id] = make_uint4(h01, h23, l01, l23);
    }
    int id2 = id - 8 * 32;
    if (id2 >= 0 && id2 < 32 * 32) {
        int pos = id2 >> 5, lane = id2 & 31;
        int n = pos >> 2, kk = pos & 3;
        int g = lane >> 2, t = lane & 3;
        int j = n * 8 + g;
        int kb = kk * 16;
        float v0 = w11[(kb + 2 * t) * 64 + j];
        float v1 = w11[(kb + 2 * t + 1) * 64 + j];
        float v2 = w11[(kb + 2 * t + 8) * 64 + j];
        float v3 = w11[(kb + 2 * t + 9) * 64 + j];
        unsigned h01, l01, h23, l23;
        f16_split(v0, v1, h01, l01);
        f16_split(v2, v3, h23, l23);
        g_W2f[pos * 32 + lane] = make_uint4(h01, h23, l01, l23);
    }

    // x fp16 image for iteration 0
    for (int i = id; i < N_NODES; i += stride) {
        const float4* xr = reinterpret_cast<const float4*>(x + (long long)i * F_IN);
        float4 xa = xr[0];
        float4 xb = xr[1];
        uint4 xs;
        xs.x = f16_pack(xa.y, xa.x);
        xs.y = f16_pack(xa.w, xa.z);
        xs.z = f16_pack(xb.y, xb.x);
        xs.w = f16_pack(xb.w, xb.z);
        g_xsA[i] = xs;
    }

    // histogram of dst
    for (int i = id; i < N_EDGES; i += stride)
        atomicAdd(&g_hist[eidx[N_EDGES + i]], 1);
}

// ---------------- scan (single block, serial chunks) ----------------
__global__ void scan_kernel() {
    __shared__ int swarp[16];
    __shared__ int srun;
    int tid = threadIdx.x, lane = tid & 31, wid = tid >> 5;
    if (tid == 0) srun = 0;
    __syncthreads();
    const int CH = (N_NODES + 511) / 512;
    for (int c = 0; c < CH; c++) {
        int i = c * 512 + tid;
        int orig = (i < N_NODES) ? g_hist[i] : 0;
        int v = orig;
#pragma unroll
        for (int off = 1; off < 32; off <<= 1) {
            int n = __shfl_up_sync(FULLM, v, off);
            if (lane >= off) v += n;
        }
        if (lane == 31) swarp[wid] = v;
        __syncthreads();
        if (wid == 0) {
            int w = (lane < 16) ? swarp[lane] : 0;
#pragma unroll
            for (int off = 1; off < 16; off <<= 1) {
                int n = __shfl_up_sync(FULLM, w, off);
                if (lane >= off) w += n;
            }
            if (lane < 16) swarp[lane] = w;
        }
        __syncthreads();
        int base = (wid > 0) ? swarp[wid - 1] : 0;
        int incl = v + base;
        int run = srun;
        int excl = run + incl - orig;
        if (i < N_NODES) { g_rowptr[i] = excl; g_offs[i] = excl; }
        __syncthreads();
        if (tid == 511) srun = run + incl;
        __syncthreads();
    }
    if (threadIdx.x == 0) g_rowptr[N_NODES] = N_EDGES;
}

// ---------------- scatter: sort edges by dst + precompute econst; re-zero hist ----------------
__global__ void scatter_kernel(const float* __restrict__ ea, const int* __restrict__ eidx) {
    int i = blockIdx.x * blockDim.x + threadIdx.x;
    int stride = gridDim.x * blockDim.x;
    if (i < N_EDGES) {
        int d = eidx[N_EDGES + i];
        int pos = atomicAdd(&g_offs[d], 1);
        g_srcs[pos] = eidx[i];
        g_dsts[pos] = d;
        const float* a = ea + (long long)i * 5;
        float a0 = a[0], a1 = a[1], a2 = a[2], a3 = a[3], a4 = a[4];
        uint4 ec;
        ec.x = f16_pack(a1, a0);
        ec.y = f16_pack(a3, a2);
        ec.z = f16_pack(1.0f, a4);   // bias slot in upper half
        ec.w = 0;
        g_econst[pos] = ec;
    }
    // re-zero histogram for the NEXT kernel_launch call (invariant: hist is clean
    // whenever prep_kernel runs; first-ever call relies on BSS zero-init)
    for (int n = i; n < N_NODES; n += stride) g_hist[n] = 0;
}

// ---------------- fused iteration kernel ----------------
// fp16 single-A-plane tensor-core edge MLP. Both GEMMs: 2 passes (A = fp16 hi, B = 2-plane).
__global__ __launch_bounds__(TPB, 2)
void fused_kernel(const float* __restrict__ x, const uint4* __restrict__ xs_in,
                  float* __restrict__ y, uint4* __restrict__ xs_out,
                  const float* __restrict__ b11,
                  const float* __restrict__ w20, const float* __restrict__ b20,
                  const float* __restrict__ w21, const float* __restrict__ b21) {
    extern __shared__ __align__(16) unsigned dynu[];
    uint4* sW1f = reinterpret_cast<uint4*>(dynu + DYN_W1F);
    uint4* sW2f = reinterpret_cast<uint4*>(dynu + DYN_W2F);

    __shared__ float sW3[72 * 32];
    __shared__ float sb20[32];
    __shared__ float sW4[32 * 5];
    __shared__ float sb21[8];
    __shared__ int   saccum[NPB * H1];
    __shared__ float sxn[NPB * F_IN];
    __shared__ float sh2[NPB * 32];
    __shared__ float so[NPB * 5];
    __shared__ int   sdst[TPB];

    int tid = threadIdx.x;
    int w = tid >> 5;
    int lane = tid & 31;
    int g = lane >> 2;   // fragment group id (0..7)
    int t = lane & 3;    // thread id in group (0..3)

    {
        const uint4* gw1 = g_W1f;
        const uint4* gw2 = g_W2f;
        for (int i = tid; i < 8 * 32; i += TPB) sW1f[i] = gw1[i];
        for (int i = tid; i < 32 * 32; i += TPB) sW2f[i] = gw2[i];
    }
    for (int i = tid; i < 72 * 32; i += TPB) sW3[i] = w20[i];
    for (int i = tid; i < 32 * 5; i += TPB) sW4[i] = w21[i];
    if (tid < 32) sb20[tid] = b20[tid];
    if (tid < 5)  sb21[tid] = b21[tid];
    for (int i = tid; i < NPB * H1; i += TPB) saccum[i] = 0;
    int nodeBase = blockIdx.x * NPB;
    if (tid < NPB * F_IN) sxn[tid] = x[nodeBase * F_IN + tid];

    // GEMM2 bias C-init for this thread's output columns
    float bj0[8], bj1[8];
#pragma unroll
    for (int n = 0; n < 8; n++) {
        bj0[n] = b11[n * 8 + 2 * t];
        bj1[n] = b11[n * 8 + 2 * t + 1];
    }
    __syncthreads();

    unsigned* scr = dynu + DYN_SCR + w * SCR_SZ;
    unsigned* A1H = scr + SCR_A1H;
    float* MSG    = reinterpret_cast<float*>(scr + SCR_MSG);

    const int e0 = g_rowptr[nodeBase];
    const int e1 = g_rowptr[nodeBase + NPB];

    for (int eb = e0; eb < e1; eb += TPB) {
        // ---- staging: precomputed fp16 pairs, no per-edge splitting ----
        {
            int e = eb + tid;
            bool act = e < e1;
            uint4 ph0 = make_uint4(0, 0, 0, 0);
            uint4 ph1 = make_uint4(0, 0, 0, 0);
            int d = 255;
            if (act) {
                int src = g_srcs[e];
                d = g_dsts[e] - nodeBase;
                ph0 = __ldg(&xs_in[src]);
                uint4 ec = __ldg(&g_econst[e]);
                ph1 = make_uint4(ec.x, ec.y, ec.z, 0);
            }
            sdst[tid] = d;
            uint4* p = reinterpret_cast<uint4*>(A1H + lane * A1_STR);
            p[0] = ph0;
            p[1] = ph1;
        }
        __syncwarp();

        // ---- process two 16-edge tiles sequentially ----
#pragma unroll 1
        for (int tile = 0; tile < 2; tile++) {
            int rb = tile * 16;

            // GEMM1 A fragments (single hi plane)
            unsigned ah0 = A1H[(rb + g) * A1_STR + t];
            unsigned ah1 = A1H[(rb + g + 8) * A1_STR + t];
            unsigned ah2 = A1H[(rb + g) * A1_STR + t + 4];
            unsigned ah3 = A1H[(rb + g + 8) * A1_STR + t + 4];

            // GEMM1 (2-pass: Ah*Bh + Ah*Bl) -> relu -> fp16 repack into GEMM2 A-fragments
            unsigned hA[8][2];
#pragma unroll
            for (int n = 0; n < 8; n++) {
                uint4 B = sW1f[n * 32 + lane];
                float c0 = 0.f, c1 = 0.f, c2 = 0.f, c3 = 0.f;
                mma_f16(c0, c1, c2, c3, ah0, ah1, ah2, ah3, B.x, B.y);
                mma_f16(c0, c1, c2, c3, ah0, ah1, ah2, ah3, B.z, B.w);
                c0 = fmaxf(c0, 0.f); c1 = fmaxf(c1, 0.f);
                c2 = fmaxf(c2, 0.f); c3 = fmaxf(c3, 0.f);
                hA[n][0] = f16_pack(c1, c0);
                hA[n][1] = f16_pack(c3, c2);
            }

            // GEMM2: K=64 (4 k-steps), 2 passes: fp16(h)*Bh + fp16(h)*Bl
            float C2[8][4];
#pragma unroll
            for (int n = 0; n < 8; n++) {
                C2[n][0] = bj0[n]; C2[n][1] = bj1[n];
                C2[n][2] = bj0[n]; C2[n][3] = bj1[n];
            }
#pragma unroll
            for (int kk = 0; kk < 4; kk++) {
                unsigned a0 = hA[2 * kk][0],     a1 = hA[2 * kk][1];
                unsigned a2 = hA[2 * kk + 1][0], a3 = hA[2 * kk + 1][1];
#pragma unroll
                for (int n = 0; n < 8; n++) {
                    uint4 B = sW2f[(n * 4 + kk) * 32 + lane];
                    mma_f16(C2[n][0], C2[n][1], C2[n][2], C2[n][3],
                            a0, a1, a2, a3, B.x, B.y);
                    mma_f16(C2[n][0], C2[n][1], C2[n][2], C2[n][3],
                            a0, a1, a2, a3, B.z, B.w);
                }
            }

            // msg tile (16 rows) with relu
#pragma unroll
            for (int n = 0; n < 8; n++) {
                float2* p0 = reinterpret_cast<float2*>(MSG + g * MSG_STRIDE + n * 8 + 2 * t);
                float2* p1 = reinterpret_cast<float2*>(MSG + (g + 8) * MSG_STRIDE + n * 8 + 2 * t);
                *p0 = make_float2(fmaxf(C2[n][0], 0.f), fmaxf(C2[n][1], 0.f));
                *p1 = make_float2(fmaxf(C2[n][2], 0.f), fmaxf(C2[n][3], 0.f));
            }
            __syncwarp();

            // segmented max over the 16 sorted rows; lane owns cols 2*lane, 2*lane+1
            {
                int cur = 255;
                float mx0 = 0.f, mx1 = 0.f;
#pragma unroll 4
                for (int r = 0; r < 16; r++) {
                    int d = sdst[w * 32 + rb + r];
                    if (d != cur) {
                        if (cur < NPB) {
                            atomicMax(&saccum[cur * H1 + 2 * lane], __float_as_int(mx0));
                            atomicMax(&saccum[cur * H1 + 2 * lane + 1], __float_as_int(mx1));
                        }
                        cur = d;
                        mx0 = 0.f; mx1 = 0.f;
                    }
                    if (d < NPB) {
                        float2 v = *reinterpret_cast<const float2*>(MSG + r * MSG_STRIDE + 2 * lane);
                        mx0 = fmaxf(mx0, v.x);
                        mx1 = fmaxf(mx1, v.y);
                    }
                }
                if (cur < NPB) {
                    atomicMax(&saccum[cur * H1 + 2 * lane], __float_as_int(mx0));
                    atomicMax(&saccum[cur * H1 + 2 * lane + 1], __float_as_int(mx1));
                }
            }
            __syncwarp();   // before next tile / next chunk reuses MSG & A1
        }
    }
    __syncthreads();

    // ---- node MLP for the block's 8 nodes ----
    {
        int s = tid >> 5, j = tid & 31;
        float acc = sb20[j];
#pragma unroll
        for (int k = 0; k < F_IN; k++)
            acc += sxn[s * F_IN + k] * sW3[k * 32 + j];
#pragma unroll 8
        for (int k = 0; k < H1; k++)
            acc += __int_as_float(saccum[s * H1 + k]) * sW3[(F_IN + k) * 32 + j];
        sh2[s * 32 + j] = fmaxf(acc, 0.f);
    }
    __syncthreads();
    if (tid < NPB * 5) {
        int s = tid / 5, jo = tid % 5;
        float acc = sb21[jo];
#pragma unroll
        for (int k = 0; k < 32; k++)
            acc += sh2[s * 32 + k] * sW4[k * 5 + jo];
        so[tid] = acc;
    }
    __syncthreads();
    if (tid < NPB) {
        int n = nodeBase + tid;
        float y0 = so[tid * 5 + 0];
        float c1 = so[tid * 5 + 1];
        float c2 = so[tid * 5 + 2];
        float c3 = so[tid * 5 + 3];
        float c4 = so[tid * 5 + 4];
        float nor = sqrtf(c1 * c1 + c2 * c2 + c3 * c3 + c4 * c4);
        float dd = fmaxf(1.f, nor);
        float y1 = c1 / dd, y2 = c2 / dd, y3 = c3 / dd, y4 = c4 / dd;
        float y5 = sxn[tid * F_IN + 0];
        float y6 = sxn[tid * F_IN + 1];
        float y7 = sxn[tid * F_IN + 2];
        float* yr = y + (long long)n * F_IN;
        yr[0] = y0; yr[1] = y1; yr[2] = y2; yr[3] = y3;
        yr[4] = y4; yr[5] = y5; yr[6] = y6; yr[7] = y7;
        // fp16 image for the next iteration (split once per node, not per edge)
        uint4 xs;
        xs.x = f16_pack(y1, y0);
        xs.y = f16_pack(y3, y2);
        xs.z = f16_pack(y5, y4);
        xs.w = f16_pack(y7, y6);
        xs_out[n] = xs;
    }
}

// ---------------- host ----------------
extern "C" void kernel_launch(void* const* d_in, const int* in_sizes, int n_in,
                              void* d_out, int out_size) {
    const float* x_in = (const float*)d_in[0];
    const float* ea   = (const float*)d_in[1];
    const int*   ei   = (const int*)d_in[2];
    const float* w10  = (const float*)d_in[3];
    const float* b10  = (const float*)d_in[4];
    const float* w11  = (const float*)d_in[5];
    const float* b11  = (const float*)d_in[6];
    const float* w20  = (const float*)d_in[7];
    const float* b20  = (const float*)d_in[8];
    const float* w21  = (const float*)d_in[9];
    const float* b21  = (const float*)d_in[10];

    float* xb[2];
    cudaGetSymbolAddress((void**)&xb[0], g_x0);
    cudaGetSymbolAddress((void**)&xb[1], g_x1);
    uint4* xs[2];
    cudaGetSymbolAddress((void**)&xs[0], g_xsA);
    cudaGetSymbolAddress((void**)&xs[1], g_xsB);

    const int dyn_bytes = DYN_UINTS * sizeof(unsigned);   // ~65 KB
    cudaFuncSetAttribute(fused_kernel, cudaFuncAttributeMaxDynamicSharedMemorySize, dyn_bytes);

    // exactly 3 pre-launches so the profiler's captured launch (#4) is fused_kernel
    prep_kernel<<<(N_EDGES + 255) / 256, 256>>>(x_in, w10, b10, w11, ei);
    scan_kernel<<<1, 512>>>();
    scatter_kernel<<<(N_EDGES + 255) / 256, 256>>>(ea, ei);

    const float* xin = x_in;
    for (int it = 0; it < N_ITERS; it++) {
        float* yout = (it == N_ITERS - 1) ? (float*)d_out : xb[it & 1];
        fused_kernel<<<NBLK, TPB, dyn_bytes>>>(xin, xs[it & 1], yout, xs[(it + 1) & 1],
                                               b11, w20, b20, w21, b21);
        xin = yout;
    }
}

// round 16
// speedup vs baseline: 5.4039x; 1.3313x over previous
#include <cuda_runtime.h>
#include <cuda_fp16.h>
#include <math.h>

// Fixed problem shapes
#define N_NODES 50000
#define N_EDGES 3200000
#define F_IN    8      // 4*NT
#define H1      64
#define NPB     8      // nodes per block
#define NBLK    (N_NODES / NPB)   // 6250
#define TPB     256
#define N_ITERS 8
#define FULLM   0xffffffffu

// dynamic smem layout in uints:
//   W1F [0,1024): 8 n-pos x 32 lanes x uint4
//   W2F [1024,5120): 32 (n,kk)-pos x 32 lanes x uint4
//   per-warp scratch @5120, 1536 uints each:
//     A1H [0,384): 32 rows x stride 12 (8 fp16x2 pairs used, single hi plane)
//     MSG [384,1536): 32 rows x stride 36, fp16x2-packed msg (cols pair-packed)
#define DYN_W1F  0
#define DYN_W2F  1024
#define DYN_SCR  5120
#define SCR_A1H  0
#define SCR_MSG  384
#define SCR_SZ   1536
#define A1_STR   12
#define MSG_STR  36
#define DYN_UINTS (5120 + 8 * SCR_SZ)   // 17408 uints = 69632 B

// ---------------- device scratch ----------------
__device__ float g_x0[N_NODES * F_IN];
__device__ float g_x1[N_NODES * F_IN];
__device__ uint4 g_xsA[N_NODES];        // fp16-pair image of node features (ping)
__device__ uint4 g_xsB[N_NODES];        // (pong)
__device__ int   g_hist[N_NODES];
__device__ int   g_rowptr[N_NODES + 1];
__device__ int   g_offs[N_NODES];
__device__ int   g_srcs[N_EDGES];
__device__ int   g_dsts[N_EDGES];
__device__ uint4 g_econst[N_EDGES];     // fp16 pairs: (a0,a1),(a2,a3),(a4,1.0),0

// fragment-ordered fp16-split weights (B side keeps 2 planes)
__device__ uint4 g_W1f[8 * 32];    // pos = n           (K=16, 1 k-step)
__device__ uint4 g_W2f[32 * 32];   // pos = n*4 + kk    (K=64, 4 k-steps)

// ---------------- fp16 helpers ----------------
__device__ __forceinline__ unsigned f16_pack(float up, float lo) {
    unsigned d;
    asm("cvt.rn.f16x2.f32 %0, %1, %2;" : "=r"(d) : "f"(up), "f"(lo));
    return d;
}
// split pair (x0 = lower element, x1 = upper element) into hi/lo fp16x2 words
__device__ __forceinline__ void f16_split(float x0, float x1, unsigned& h2, unsigned& l2) {
    h2 = f16_pack(x1, x0);
    __half2 hv = *reinterpret_cast<__half2*>(&h2);
    float2 f = __half22float2(hv);
    l2 = f16_pack(x1 - f.y, x0 - f.x);
}
__device__ __forceinline__ void mma_f16(float& c0, float& c1, float& c2, float& c3,
                                        unsigned a0, unsigned a1, unsigned a2, unsigned a3,
                                        unsigned b0, unsigned b1) {
    asm("mma.sync.aligned.m16n8k16.row.col.f32.f16.f16.f32 "
        "{%0,%1,%2,%3}, {%4,%5,%6,%7}, {%8,%9}, {%0,%1,%2,%3};"
        : "+f"(c0), "+f"(c1), "+f"(c2), "+f"(c3)
        : "r"(a0), "r"(a1), "r"(a2), "r"(a3), "r"(b0), "r"(b1));
}

// ---------------- prep: weight fragments + x fp16 image + histogram ----------------
// g_hist is zeroed by the END of the previous call's scatter_kernel (BSS-zero on
// first call), so the atomics here always see a clean histogram.
__device__ __forceinline__ float w1eff(const float* w10, const float* b10, int k, int j) {
    if (k < 13) return w10[k * 64 + j];
    if (k == 13) return b10[j];
    return 0.f;
}

__global__ void prep_kernel(const float* __restrict__ x,
                            const float* __restrict__ w10, const float* __restrict__ b10,
                            const float* __restrict__ w11,
                            const int* __restrict__ eidx) {
    int id = blockIdx.x * blockDim.x + threadIdx.x;
    int stride = gridDim.x * blockDim.x;

    if (id < 8 * 32) {
        int n = id >> 5, lane = id & 31;
        int g = lane >> 2, t = lane & 3;
        int j = n * 8 + g;
        float v0 = w1eff(w10, b10, 2 * t, j);
        float v1 = w1eff(w10, b10, 2 * t + 1, j);
        float v2 = w1eff(w10, b10, 2 * t + 8, j);
        float v3 = w1eff(w10, b10, 2 * t + 9, j);
        unsigned h01, l01, h23, l23;
        f16_split(v0, v1, h01, l01);
        f16_split(v2, v3, h23, l23);
        g_W1f[id] = make_uint4(h01, h23, l01, l23);
    }
    int id2 = id - 8 * 32;
    if (id2 >= 0 && id2 < 32 * 32) {
        int pos = id2 >> 5, lane = id2 & 31;
        int n = pos >> 2, kk = pos & 3;
        int g = lane >> 2, t = lane & 3;
        int j = n * 8 + g;
        int kb = kk * 16;
        float v0 = w11[(kb + 2 * t) * 64 + j];
        float v1 = w11[(kb + 2 * t + 1) * 64 + j];
        float v2 = w11[(kb + 2 * t + 8) * 64 + j];
        float v3 = w11[(kb + 2 * t + 9) * 64 + j];
        unsigned h01, l01, h23, l23;
        f16_split(v0, v1, h01, l01);
        f16_split(v2, v3, h23, l23);
        g_W2f[pos * 32 + lane] = make_uint4(h01, h23, l01, l23);
    }

    // x fp16 image for iteration 0
    for (int i = id; i < N_NODES; i += stride) {
        const float4* xr = reinterpret_cast<const float4*>(x + (long long)i * F_IN);
        float4 xa = xr[0];
        float4 xb = xr[1];
        uint4 xs;
        xs.x = f16_pack(xa.y, xa.x);
        xs.y = f16_pack(xa.w, xa.z);
        xs.z = f16_pack(xb.y, xb.x);
        xs.w = f16_pack(xb.w, xb.z);
        g_xsA[i] = xs;
    }

    // histogram of dst
    for (int i = id; i < N_EDGES; i += stride)
        atomicAdd(&g_hist[eidx[N_EDGES + i]], 1);
}

// ---------------- scan (single block, serial chunks) ----------------
__global__ void scan_kernel() {
    __shared__ int swarp[16];
    __shared__ int srun;
    int tid = threadIdx.x, lane = tid & 31, wid = tid >> 5;
    if (tid == 0) srun = 0;
    __syncthreads();
    const int CH = (N_NODES + 511) / 512;
    for (int c = 0; c < CH; c++) {
        int i = c * 512 + tid;
        int orig = (i < N_NODES) ? g_hist[i] : 0;
        int v = orig;
#pragma unroll
        for (int off = 1; off < 32; off <<= 1) {
            int n = __shfl_up_sync(FULLM, v, off);
            if (lane >= off) v += n;
        }
        if (lane == 31) swarp[wid] = v;
        __syncthreads();
        if (wid == 0) {
            int w = (lane < 16) ? swarp[lane] : 0;
#pragma unroll
            for (int off = 1; off < 16; off <<= 1) {
                int n = __shfl_up_sync(FULLM, w, off);
                if (lane >= off) w += n;
            }
            if (lane < 16) swarp[lane] = w;
        }
        __syncthreads();
        int base = (wid > 0) ? swarp[wid - 1] : 0;
        int incl = v + base;
        int run = srun;
        int excl = run + incl - orig;
        if (i < N_NODES) { g_rowptr[i] = excl; g_offs[i] = excl; }
        __syncthreads();
        if (tid == 511) srun = run + incl;
        __syncthreads();
    }
    if (threadIdx.x == 0) g_rowptr[N_NODES] = N_EDGES;
}

// ---------------- scatter: sort edges by dst + precompute econst; re-zero hist ----------------
__global__ void scatter_kernel(const float* __restrict__ ea, const int* __restrict__ eidx) {
    int i = blockIdx.x * blockDim.x + threadIdx.x;
    int stride = gridDim.x * blockDim.x;
    if (i < N_EDGES) {
        int d = eidx[N_EDGES + i];
        int pos = atomicAdd(&g_offs[d], 1);
        g_srcs[pos] = eidx[i];
        g_dsts[pos] = d;
        const float* a = ea + (long long)i * 5;
        float a0 = a[0], a1 = a[1], a2 = a[2], a3 = a[3], a4 = a[4];
        uint4 ec;
        ec.x = f16_pack(a1, a0);
        ec.y = f16_pack(a3, a2);
        ec.z = f16_pack(1.0f, a4);   // bias slot in upper half
        ec.w = 0;
        g_econst[pos] = ec;
    }
    // re-zero histogram for the NEXT kernel_launch call
    for (int n = i; n < N_NODES; n += stride) g_hist[n] = 0;
}

// ---------------- fused iteration kernel ----------------
// fp16 single-A-plane tensor-core edge MLP; B-fragment loads shared across both
// 16-edge tiles (n-outer loops); msg staged as packed fp16x2.
__global__ __launch_bounds__(TPB, 2)
void fused_kernel(const float* __restrict__ x, const uint4* __restrict__ xs_in,
                  float* __restrict__ y, uint4* __restrict__ xs_out,
                  const float* __restrict__ b11,
                  const float* __restrict__ w20, const float* __restrict__ b20,
                  const float* __restrict__ w21, const float* __restrict__ b21) {
    extern __shared__ __align__(16) unsigned dynu[];
    uint4* sW1f = reinterpret_cast<uint4*>(dynu + DYN_W1F);
    uint4* sW2f = reinterpret_cast<uint4*>(dynu + DYN_W2F);

    __shared__ float sW3[72 * 32];
    __shared__ float sb20[32];
    __shared__ float sW4[32 * 5];
    __shared__ float sb21[8];
    __shared__ int   saccum[NPB * H1];
    __shared__ float sxn[NPB * F_IN];
    __shared__ float sh2[NPB * 32];
    __shared__ float so[NPB * 5];
    __shared__ int   sdst[TPB];

    int tid = threadIdx.x;
    int w = tid >> 5;
    int lane = tid & 31;
    int g = lane >> 2;   // fragment group id (0..7)
    int t = lane & 3;    // thread id in group (0..3)

    {
        const uint4* gw1 = g_W1f;
        const uint4* gw2 = g_W2f;
        for (int i = tid; i < 8 * 32; i += TPB) sW1f[i] = gw1[i];
        for (int i = tid; i < 32 * 32; i += TPB) sW2f[i] = gw2[i];
    }
    for (int i = tid; i < 72 * 32; i += TPB) sW3[i] = w20[i];
    for (int i = tid; i < 32 * 5; i += TPB) sW4[i] = w21[i];
    if (tid < 32) sb20[tid] = b20[tid];
    if (tid < 5)  sb21[tid] = b21[tid];
    for (int i = tid; i < NPB * H1; i += TPB) saccum[i] = 0;
    int nodeBase = blockIdx.x * NPB;
    if (tid < NPB * F_IN) sxn[tid] = x[nodeBase * F_IN + tid];

    // GEMM2 bias C-init for this thread's output columns
    float bj0[8], bj1[8];
#pragma unroll
    for (int n = 0; n < 8; n++) {
        bj0[n] = b11[n * 8 + 2 * t];
        bj1[n] = b11[n * 8 + 2 * t + 1];
    }
    __syncthreads();

    unsigned* scr = dynu + DYN_SCR + w * SCR_SZ;
    unsigned* A1H = scr + SCR_A1H;
    unsigned* MSG = scr + SCR_MSG;

    const int e0 = g_rowptr[nodeBase];
    const int e1 = g_rowptr[nodeBase + NPB];

    // packed column this lane owns in the segmax phase: p = lane -> cols (8n+2t, +1)
    const int segCol = 8 * (lane >> 2) + 2 * (lane & 3);

    for (int eb = e0; eb < e1; eb += TPB) {
        // ---- staging: precomputed fp16 pairs, no per-edge splitting ----
        {
            int e = eb + tid;
            bool act = e < e1;
            uint4 ph0 = make_uint4(0, 0, 0, 0);
            uint4 ph1 = make_uint4(0, 0, 0, 0);
            int d = 255;
            if (act) {
                int src = g_srcs[e];
                d = g_dsts[e] - nodeBase;
                ph0 = __ldg(&xs_in[src]);
                uint4 ec = __ldg(&g_econst[e]);
                ph1 = make_uint4(ec.x, ec.y, ec.z, 0);
            }
            sdst[tid] = d;
            uint4* p = reinterpret_cast<uint4*>(A1H + lane * A1_STR);
            p[0] = ph0;
            p[1] = ph1;
        }
        __syncwarp();

        // ---- GEMM1 A fragments for BOTH tiles (single hi plane) ----
        unsigned ag0[2], ag1[2], ag2[2], ag3[2];
#pragma unroll
        for (int tile = 0; tile < 2; tile++) {
            int rb = tile * 16;
            ag0[tile] = A1H[(rb + g) * A1_STR + t];
            ag1[tile] = A1H[(rb + g + 8) * A1_STR + t];
            ag2[tile] = A1H[(rb + g) * A1_STR + t + 4];
            ag3[tile] = A1H[(rb + g + 8) * A1_STR + t + 4];
        }

        // ---- GEMM1: n-outer, B loaded ONCE per n for both tiles ----
        unsigned hA[2][8][2];
#pragma unroll
        for (int n = 0; n < 8; n++) {
            uint4 B = sW1f[n * 32 + lane];
#pragma unroll
            for (int tile = 0; tile < 2; tile++) {
                float c0 = 0.f, c1 = 0.f, c2 = 0.f, c3 = 0.f;
                mma_f16(c0, c1, c2, c3, ag0[tile], ag1[tile], ag2[tile], ag3[tile], B.x, B.y);
                mma_f16(c0, c1, c2, c3, ag0[tile], ag1[tile], ag2[tile], ag3[tile], B.z, B.w);
                c0 = fmaxf(c0, 0.f); c1 = fmaxf(c1, 0.f);
                c2 = fmaxf(c2, 0.f); c3 = fmaxf(c3, 0.f);
                hA[tile][n][0] = f16_pack(c1, c0);
                hA[tile][n][1] = f16_pack(c3, c2);
            }
        }

        // ---- GEMM2: n-outer / kk-inner, B loaded once per (n,kk) for both tiles;
        //      per-n accumulators only; msg written packed fp16x2 ----
#pragma unroll
        for (int n = 0; n < 8; n++) {
            float C[2][4];
#pragma unroll
            for (int tile = 0; tile < 2; tile++) {
                C[tile][0] = bj0[n]; C[tile][1] = bj1[n];
                C[tile][2] = bj0[n]; C[tile][3] = bj1[n];
            }
#pragma unroll
            for (int kk = 0; kk < 4; kk++) {
                uint4 B = sW2f[(n * 4 + kk) * 32 + lane];
#pragma unroll
                for (int tile = 0; tile < 2; tile++) {
                    unsigned a0 = hA[tile][2 * kk][0],     a1 = hA[tile][2 * kk][1];
                    unsigned a2 = hA[tile][2 * kk + 1][0], a3 = hA[tile][2 * kk + 1][1];
                    mma_f16(C[tile][0], C[tile][1], C[tile][2], C[tile][3],
                            a0, a1, a2, a3, B.x, B.y);
                    mma_f16(C[tile][0], C[tile][1], C[tile][2], C[tile][3],
                            a0, a1, a2, a3, B.z, B.w);
                }
            }
            int p = n * 4 + t;
#pragma unroll
            for (int tile = 0; tile < 2; tile++) {
                int rb = tile * 16;
                float m0 = fmaxf(C[tile][0], 0.f);
                float m1 = fmaxf(C[tile][1], 0.f);
                float m2 = fmaxf(C[tile][2], 0.f);
                float m3 = fmaxf(C[tile][3], 0.f);
                MSG[(rb + g) * MSG_STR + p]     = f16_pack(m1, m0);
                MSG[(rb + g + 8) * MSG_STR + p] = f16_pack(m3, m2);
            }
        }
        __syncwarp();

        // ---- segmented max over ALL 32 sorted rows; lane owns packed col `lane` ----
        {
            int cur = 255;
            float mx0 = 0.f, mx1 = 0.f;
#pragma unroll 4
            for (int r = 0; r < 32; r++) {
                int d = sdst[w * 32 + r];
                if (d != cur) {
                    if (cur < NPB) {
                        atomicMax(&saccum[cur * H1 + segCol], __float_as_int(mx0));
                        atomicMax(&saccum[cur * H1 + segCol + 1], __float_as_int(mx1));
                    }
                    cur = d;
                    mx0 = 0.f; mx1 = 0.f;
                }
                if (d < NPB) {
                    unsigned pv = MSG[r * MSG_STR + lane];
                    float2 v = __half22float2(*reinterpret_cast<__half2*>(&pv));
                    mx0 = fmaxf(mx0, v.x);
                    mx1 = fmaxf(mx1, v.y);
                }
            }
            if (cur < NPB) {
                atomicMax(&saccum[cur * H1 + segCol], __float_as_int(mx0));
                atomicMax(&saccum[cur * H1 + segCol + 1], __float_as_int(mx1));
            }
        }
        __syncwarp();   // before next chunk reuses MSG & A1
    }
    __syncthreads();

    // ---- node MLP for the block's 8 nodes ----
    {
        int s = tid >> 5, j = tid & 31;
        float acc = sb20[j];
#pragma unroll
        for (int k = 0; k < F_IN; k++)
            acc += sxn[s * F_IN + k] * sW3[k * 32 + j];
#pragma unroll 8
        for (int k = 0; k < H1; k++)
            acc += __int_as_float(saccum[s * H1 + k]) * sW3[(F_IN + k) * 32 + j];
        sh2[s * 32 + j] = fmaxf(acc, 0.f);
    }
    __syncthreads();
    if (tid < NPB * 5) {
        int s = tid / 5, jo = tid % 5;
        float acc = sb21[jo];
#pragma unroll
        for (int k = 0; k < 32; k++)
            acc += sh2[s * 32 + k] * sW4[k * 5 + jo];
        so[tid] = acc;
    }
    __syncthreads();
    if (tid < NPB) {
        int n = nodeBase + tid;
        float y0 = so[tid * 5 + 0];
        float c1 = so[tid * 5 + 1];
        float c2 = so[tid * 5 + 2];
        float c3 = so[tid * 5 + 3];
        float c4 = so[tid * 5 + 4];
        float nor = sqrtf(c1 * c1 + c2 * c2 + c3 * c3 + c4 * c4);
        float dd = fmaxf(1.f, nor);
        float y1 = c1 / dd, y2 = c2 / dd, y3 = c3 / dd, y4 = c4 / dd;
        float y5 = sxn[tid * F_IN + 0];
        float y6 = sxn[tid * F_IN + 1];
        float y7 = sxn[tid * F_IN + 2];
        float* yr = y + (long long)n * F_IN;
        yr[0] = y0; yr[1] = y1; yr[2] = y2; yr[3] = y3;
        yr[4] = y4; yr[5] = y5; yr[6] = y6; yr[7] = y7;
        // fp16 image for the next iteration (split once per node, not per edge)
        uint4 xs;
        xs.x = f16_pack(y1, y0);
        xs.y = f16_pack(y3, y2);
        xs.z = f16_pack(y5, y4);
        xs.w = f16_pack(y7, y6);
        xs_out[n] = xs;
    }
}

// ---------------- host ----------------
extern "C" void kernel_launch(void* const* d_in, const int* in_sizes, int n_in,
                              void* d_out, int out_size) {
    const float* x_in = (const float*)d_in[0];
    const float* ea   = (const float*)d_in[1];
    const int*   ei   = (const int*)d_in[2];
    const float* w10  = (const float*)d_in[3];
    const float* b10  = (const float*)d_in[4];
    const float* w11  = (const float*)d_in[5];
    const float* b11  = (const float*)d_in[6];
    const float* w20  = (const float*)d_in[7];
    const float* b20  = (const float*)d_in[8];
    const float* w21  = (const float*)d_in[9];
    const float* b21  = (const float*)d_in[10];

    float* xb[2];
    cudaGetSymbolAddress((void**)&xb[0], g_x0);
    cudaGetSymbolAddress((void**)&xb[1], g_x1);
    uint4* xs[2];
    cudaGetSymbolAddress((void**)&xs[0], g_xsA);
    cudaGetSymbolAddress((void**)&xs[1], g_xsB);

    const int dyn_bytes = DYN_UINTS * sizeof(unsigned);   // ~68 KB
    cudaFuncSetAttribute(fused_kernel, cudaFuncAttributeMaxDynamicSharedMemorySize, dyn_bytes);

    // exactly 3 pre-launches so the profiler's captured launch (#4) is fused_kernel
    prep_kernel<<<(N_EDGES + 255) / 256, 256>>>(x_in, w10, b10, w11, ei);
    scan_kernel<<<1, 512>>>();
    scatter_kernel<<<(N_EDGES + 255) / 256, 256>>>(ea, ei);

    const float* xin = x_in;
    for (int it = 0; it < N_ITERS; it++) {
        float* yout = (it == N_ITERS - 1) ? (float*)d_out : xb[it & 1];
        fused_kernel<<<NBLK, TPB, dyn_bytes>>>(xin, xs[it & 1], yout, xs[(it + 1) & 1],
                                               b11, w20, b20, w21, b21);
        xin = yout;
    }
}

// round 17
// speedup vs baseline: 6.1784x; 1.1433x over previous
#include <cuda_runtime.h>
#include <cuda_fp16.h>
#include <math.h>

// Fixed problem shapes
#define N_NODES 50000
#define N_EDGES 3200000
#define F_IN    8      // 4*NT
#define H1      64
#define NPB     8      // nodes per block
#define NBLK    (N_NODES / NPB)   // 6250
#define TPB     256
#define N_ITERS 8
#define FULLM   0xffffffffu

// dynamic smem layout in uints:
//   W1F [0,1024): 8 n-pos x 32 lanes x uint4
//   W2F [1024,5120): 32 (n,kk)-pos x 32 lanes x uint4
//   per-warp scratch @5120, 384 uints each:
//     A1H: 32 rows x stride 12 (8 fp16x2 pairs used, single hi plane)
#define DYN_W1F  0
#define DYN_W2F  1024
#define DYN_SCR  5120
#define SCR_SZ   384
#define A1_STR   12
#define DYN_UINTS (5120 + 8 * SCR_SZ)   // 8192 uints = 32768 B

// ---------------- device scratch ----------------
__device__ float g_x0[N_NODES * F_IN];
__device__ float g_x1[N_NODES * F_IN];
__device__ uint4 g_xsA[N_NODES];        // fp16-pair image of node features (ping)
__device__ uint4 g_xsB[N_NODES];        // (pong)
__device__ int   g_hist[N_NODES];
__device__ int   g_rowptr[N_NODES + 1];
__device__ int   g_offs[N_NODES];
__device__ int   g_srcs[N_EDGES];
__device__ int   g_dsts[N_EDGES];
__device__ uint4 g_econst[N_EDGES];     // fp16 pairs: (a0,a1),(a2,a3),(a4,1.0),0

// fragment-ordered fp16-split weights (B side keeps 2 planes)
__device__ uint4 g_W1f[8 * 32];    // pos = n           (K=16, 1 k-step)
__device__ uint4 g_W2f[32 * 32];   // pos = n*4 + kk    (K=64, 4 k-steps)

// ---------------- fp16 helpers ----------------
__device__ __forceinline__ unsigned f16_pack(float up, float lo) {
    unsigned d;
    asm("cvt.rn.f16x2.f32 %0, %1, %2;" : "=r"(d) : "f"(up), "f"(lo));
    return d;
}
// split pair (x0 = lower element, x1 = upper element) into hi/lo fp16x2 words
__device__ __forceinline__ void f16_split(float x0, float x1, unsigned& h2, unsigned& l2) {
    h2 = f16_pack(x1, x0);
    __half2 hv = *reinterpret_cast<__half2*>(&h2);
    float2 f = __half22float2(hv);
    l2 = f16_pack(x1 - f.y, x0 - f.x);
}
__device__ __forceinline__ void mma_f16(float& c0, float& c1, float& c2, float& c3,
                                        unsigned a0, unsigned a1, unsigned a2, unsigned a3,
                                        unsigned b0, unsigned b1) {
    asm("mma.sync.aligned.m16n8k16.row.col.f32.f16.f16.f32 "
        "{%0,%1,%2,%3}, {%4,%5,%6,%7}, {%8,%9}, {%0,%1,%2,%3};"
        : "+f"(c0), "+f"(c1), "+f"(c2), "+f"(c3)
        : "r"(a0), "r"(a1), "r"(a2), "r"(a3), "r"(b0), "r"(b1));
}

// ---------------- prep: weight fragments + x fp16 image + histogram ----------------
// g_hist is zeroed by the END of the previous call's scatter_kernel (BSS-zero on
// first call), so the atomics here always see a clean histogram.
__device__ __forceinline__ float w1eff(const float* w10, const float* b10, int k, int j) {
    if (k < 13) return w10[k * 64 + j];
    if (k == 13) return b10[j];
    return 0.f;
}

__global__ void prep_kernel(const float* __restrict__ x,
                            const float* __restrict__ w10, const float* __restrict__ b10,
                            const float* __restrict__ w11,
                            const int* __restrict__ eidx) {
    int id = blockIdx.x * blockDim.x + threadIdx.x;
    int stride = gridDim.x * blockDim.x;

    if (id < 8 * 32) {
        int n = id >> 5, lane = id & 31;
        int g = lane >> 2, t = lane & 3;
        int j = n * 8 + g;
        float v0 = w1eff(w10, b10, 2 * t, j);
        float v1 = w1eff(w10, b10, 2 * t + 1, j);
        float v2 = w1eff(w10, b10, 2 * t + 8, j);
        float v3 = w1eff(w10, b10, 2 * t + 9, j);
        unsigned h01, l01, h23, l23;
        f16_split(v0, v1, h01, l01);
        f16_split(v2, v3, h23, l23);
        g_W1f[id] = make_uint4(h01, h23, l01, l23);
    }
    int id2 = id - 8 * 32;
    if (id2 >= 0 && id2 < 32 * 32) {
        int pos = id2 >> 5, lane = id2 & 31;
        int n = pos >> 2, kk = pos & 3;
        int g = lane >> 2, t = lane & 3;
        int j = n * 8 + g;
        int kb = kk * 16;
        float v0 = w11[(kb + 2 * t) * 64 + j];
        float v1 = w11[(kb + 2 * t + 1) * 64 + j];
        float v2 = w11[(kb + 2 * t + 8) * 64 + j];
        float v3 = w11[(kb + 2 * t + 9) * 64 + j];
        unsigned h01, l01, h23, l23;
        f16_split(v0, v1, h01, l01);
        f16_split(v2, v3, h23, l23);
        g_W2f[pos * 32 + lane] = make_uint4(h01, h23, l01, l23);
    }

    // x fp16 image for iteration 0
    for (int i = id; i < N_NODES; i += stride) {
        const float4* xr = reinterpret_cast<const float4*>(x + (long long)i * F_IN);
        float4 xa = xr[0];
        float4 xb = xr[1];
        uint4 xs;
        xs.x = f16_pack(xa.y, xa.x);
        xs.y = f16_pack(xa.w, xa.z);
        xs.z = f16_pack(xb.y, xb.x);
        xs.w = f16_pack(xb.w, xb.z);
        g_xsA[i] = xs;
    }

    // histogram of dst
    for (int i = id; i < N_EDGES; i += stride)
        atomicAdd(&g_hist[eidx[N_EDGES + i]], 1);
}

// ---------------- scan (single block, serial chunks) ----------------
__global__ void scan_kernel() {
    __shared__ int swarp[16];
    __shared__ int srun;
    int tid = threadIdx.x, lane = tid & 31, wid = tid >> 5;
    if (tid == 0) srun = 0;
    __syncthreads();
    const int CH = (N_NODES + 511) / 512;
    for (int c = 0; c < CH; c++) {
        int i = c * 512 + tid;
        int orig = (i < N_NODES) ? g_hist[i] : 0;
        int v = orig;
#pragma unroll
        for (int off = 1; off < 32; off <<= 1) {
            int n = __shfl_up_sync(FULLM, v, off);
            if (lane >= off) v += n;
        }
        if (lane == 31) swarp[wid] = v;
        __syncthreads();
        if (wid == 0) {
            int w = (lane < 16) ? swarp[lane] : 0;
#pragma unroll
            for (int off = 1; off < 16; off <<= 1) {
                int n = __shfl_up_sync(FULLM, w, off);
                if (lane >= off) w += n;
            }
            if (lane < 16) swarp[lane] = w;
        }
        __syncthreads();
        int base = (wid > 0) ? swarp[wid - 1] : 0;
        int incl = v + base;
        int run = srun;
        int excl = run + incl - orig;
        if (i < N_NODES) { g_rowptr[i] = excl; g_offs[i] = excl; }
        __syncthreads();
        if (tid == 511) srun = run + incl;
        __syncthreads();
    }
    if (threadIdx.x == 0) g_rowptr[N_NODES] = N_EDGES;
}

// ---------------- scatter: sort edges by dst + precompute econst; re-zero hist ----------------
__global__ void scatter_kernel(const float* __restrict__ ea, const int* __restrict__ eidx) {
    int i = blockIdx.x * blockDim.x + threadIdx.x;
    int stride = gridDim.x * blockDim.x;
    if (i < N_EDGES) {
        int d = eidx[N_EDGES + i];
        int pos = atomicAdd(&g_offs[d], 1);
        g_srcs[pos] = eidx[i];
        g_dsts[pos] = d;
        const float* a = ea + (long long)i * 5;
        float a0 = a[0], a1 = a[1], a2 = a[2], a3 = a[3], a4 = a[4];
        uint4 ec;
        ec.x = f16_pack(a1, a0);
        ec.y = f16_pack(a3, a2);
        ec.z = f16_pack(1.0f, a4);   // bias slot in upper half
        ec.w = 0;
        g_econst[pos] = ec;
    }
    // re-zero histogram for the NEXT kernel_launch call
    for (int n = i; n < N_NODES; n += stride) g_hist[n] = 0;
}

// ---------------- fused iteration kernel ----------------
// fp16 single-A-plane tensor-core edge MLP; B-fragment loads shared across both
// 16-edge tiles; segmented max done fully in registers via dst-value loop + shfl.
__global__ __launch_bounds__(TPB, 3)
void fused_kernel(const float* __restrict__ x, const uint4* __restrict__ xs_in,
                  float* __restrict__ y, uint4* __restrict__ xs_out,
                  const float* __restrict__ b11,
                  const float* __restrict__ w20, const float* __restrict__ b20,
                  const float* __restrict__ w21, const float* __restrict__ b21) {
    extern __shared__ __align__(16) unsigned dynu[];
    uint4* sW1f = reinterpret_cast<uint4*>(dynu + DYN_W1F);
    uint4* sW2f = reinterpret_cast<uint4*>(dynu + DYN_W2F);

    __shared__ float sW3[72 * 32];
    __shared__ float sb20[32];
    __shared__ float sW4[32 * 5];
    __shared__ float sb21[8];
    __shared__ float sb11[H1];
    __shared__ int   saccum[NPB * H1];
    __shared__ float sxn[NPB * F_IN];
    __shared__ float sh2[NPB * 32];
    __shared__ float so[NPB * 5];
    __shared__ int   sdst[TPB];

    int tid = threadIdx.x;
    int w = tid >> 5;
    int lane = tid & 31;
    int g = lane >> 2;   // fragment group id (0..7)
    int t = lane & 3;    // thread id in group (0..3)

    {
        const uint4* gw1 = g_W1f;
        const uint4* gw2 = g_W2f;
        for (int i = tid; i < 8 * 32; i += TPB) sW1f[i] = gw1[i];
        for (int i = tid; i < 32 * 32; i += TPB) sW2f[i] = gw2[i];
    }
    for (int i = tid; i < 72 * 32; i += TPB) sW3[i] = w20[i];
    for (int i = tid; i < 32 * 5; i += TPB) sW4[i] = w21[i];
    if (tid < 32) sb20[tid] = b20[tid];
    if (tid < 5)  sb21[tid] = b21[tid];
    if (tid < H1) sb11[tid] = b11[tid];
    for (int i = tid; i < NPB * H1; i += TPB) saccum[i] = 0;
    int nodeBase = blockIdx.x * NPB;
    if (tid < NPB * F_IN) sxn[tid] = x[nodeBase * F_IN + tid];
    __syncthreads();

    unsigned* A1H = dynu + DYN_SCR + w * SCR_SZ;

    const int e0 = g_rowptr[nodeBase];
    const int e1 = g_rowptr[nodeBase + NPB];

    for (int eb = e0; eb < e1; eb += TPB) {
        // ---- staging: precomputed fp16 pairs, no per-edge splitting ----
        {
            int e = eb + tid;
            bool act = e < e1;
            uint4 ph0 = make_uint4(0, 0, 0, 0);
            uint4 ph1 = make_uint4(0, 0, 0, 0);
            int d = 255;
            if (act) {
                int src = g_srcs[e];
                d = g_dsts[e] - nodeBase;
                ph0 = __ldg(&xs_in[src]);
                uint4 ec = __ldg(&g_econst[e]);
                ph1 = make_uint4(ec.x, ec.y, ec.z, 0);
            }
            sdst[tid] = d;
            uint4* p = reinterpret_cast<uint4*>(A1H + lane * A1_STR);
            p[0] = ph0;
            p[1] = ph1;
        }
        __syncwarp();

        // per-thread row dsts (rows g, g+8 of tile0; 16+g, 24+g of tile1)
        int dq0 = sdst[w * 32 + g];
        int dq1 = sdst[w * 32 + g + 8];
        int dq2 = sdst[w * 32 + 16 + g];
        int dq3 = sdst[w * 32 + 24 + g];
        int dlo = sdst[w * 32];
        int dhi = sdst[w * 32 + 31];
        if (dhi > NPB - 1) dhi = NPB - 1;
        bool doSeg = (dlo < NPB);

        // ---- GEMM1 A fragments for BOTH tiles (single hi plane) ----
        unsigned ag0[2], ag1[2], ag2[2], ag3[2];
#pragma unroll
        for (int tile = 0; tile < 2; tile++) {
            int rb = tile * 16;
            ag0[tile] = A1H[(rb + g) * A1_STR + t];
            ag1[tile] = A1H[(rb + g + 8) * A1_STR + t];
            ag2[tile] = A1H[(rb + g) * A1_STR + t + 4];
            ag3[tile] = A1H[(rb + g + 8) * A1_STR + t + 4];
        }

        // ---- GEMM1: n-outer, B loaded ONCE per n for both tiles ----
        unsigned hA[2][8][2];
#pragma unroll
        for (int n = 0; n < 8; n++) {
            uint4 B = sW1f[n * 32 + lane];
#pragma unroll
            for (int tile = 0; tile < 2; tile++) {
                float c0 = 0.f, c1 = 0.f, c2 = 0.f, c3 = 0.f;
                mma_f16(c0, c1, c2, c3, ag0[tile], ag1[tile], ag2[tile], ag3[tile], B.x, B.y);
                mma_f16(c0, c1, c2, c3, ag0[tile], ag1[tile], ag2[tile], ag3[tile], B.z, B.w);
                c0 = fmaxf(c0, 0.f); c1 = fmaxf(c1, 0.f);
                c2 = fmaxf(c2, 0.f); c3 = fmaxf(c3, 0.f);
                hA[tile][n][0] = f16_pack(c1, c0);
                hA[tile][n][1] = f16_pack(c3, c2);
            }
        }

        // ---- GEMM2: n-outer / kk-inner + in-register segmented max ----
#pragma unroll
        for (int n = 0; n < 8; n++) {
            float b0 = sb11[n * 8 + 2 * t];
            float b1 = sb11[n * 8 + 2 * t + 1];
            float C[2][4];
#pragma unroll
            for (int tile = 0; tile < 2; tile++) {
                C[tile][0] = b0; C[tile][1] = b1;
                C[tile][2] = b0; C[tile][3] = b1;
            }
#pragma unroll
            for (int kk = 0; kk < 4; kk++) {
                uint4 B = sW2f[(n * 4 + kk) * 32 + lane];
#pragma unroll
                for (int tile = 0; tile < 2; tile++) {
                    unsigned a0 = hA[tile][2 * kk][0],     a1 = hA[tile][2 * kk][1];
                    unsigned a2 = hA[tile][2 * kk + 1][0], a3 = hA[tile][2 * kk + 1][1];
                    mma_f16(C[tile][0], C[tile][1], C[tile][2], C[tile][3],
                            a0, a1, a2, a3, B.x, B.y);
                    mma_f16(C[tile][0], C[tile][1], C[tile][2], C[tile][3],
                            a0, a1, a2, a3, B.z, B.w);
                }
            }
            // relu (msg values; rows: dq0 -> C[0][0/1], dq1 -> C[0][2/3],
            //                         dq2 -> C[1][0/1], dq3 -> C[1][2/3])
            float v00 = fmaxf(C[0][0], 0.f), v01 = fmaxf(C[0][1], 0.f);
            float v02 = fmaxf(C[0][2], 0.f), v03 = fmaxf(C[0][3], 0.f);
            float v10 = fmaxf(C[1][0], 0.f), v11 = fmaxf(C[1][1], 0.f);
            float v12 = fmaxf(C[1][2], 0.f), v13 = fmaxf(C[1][3], 0.f);

            if (doSeg) {
#pragma unroll 1
                for (int d = dlo; d <= dhi; d++) {
                    float mx0 = fmaxf(fmaxf(dq0 == d ? v00 : 0.f, dq1 == d ? v02 : 0.f),
                                      fmaxf(dq2 == d ? v10 : 0.f, dq3 == d ? v12 : 0.f));
                    float mx1 = fmaxf(fmaxf(dq0 == d ? v01 : 0.f, dq1 == d ? v03 : 0.f),
                                      fmaxf(dq2 == d ? v11 : 0.f, dq3 == d ? v13 : 0.f));
                    mx0 = fmaxf(mx0, __shfl_down_sync(FULLM, mx0, 4));
                    mx1 = fmaxf(mx1, __shfl_down_sync(FULLM, mx1, 4));
                    mx0 = fmaxf(mx0, __shfl_down_sync(FULLM, mx0, 8));
                    mx1 = fmaxf(mx1, __shfl_down_sync(FULLM, mx1, 8));
                    mx0 = fmaxf(mx0, __shfl_down_sync(FULLM, mx0, 16));
                    mx1 = fmaxf(mx1, __shfl_down_sync(FULLM, mx1, 16));
                    if (g == 0) {
                        atomicMax(&saccum[d * H1 + n * 8 + 2 * t], __float_as_int(mx0));
                        atomicMax(&saccum[d * H1 + n * 8 + 2 * t + 1], __float_as_int(mx1));
                    }
                }
            }
        }
        __syncwarp();   // before next chunk reuses A1H / sdst
    }
    __syncthreads();

    // ---- node MLP for the block's 8 nodes ----
    {
        int s = tid >> 5, j = tid & 31;
        float acc = sb20[j];
#pragma unroll
        for (int k = 0; k < F_IN; k++)
            acc += sxn[s * F_IN + k] * sW3[k * 32 + j];
#pragma unroll 8
        for (int k = 0; k < H1; k++)
            acc += __int_as_float(saccum[s * H1 + k]) * sW3[(F_IN + k) * 32 + j];
        sh2[s * 32 + j] = fmaxf(acc, 0.f);
    }
    __syncthreads();
    if (tid < NPB * 5) {
        int s = tid / 5, jo = tid % 5;
        float acc = sb21[jo];
#pragma unroll
        for (int k = 0; k < 32; k++)
            acc += sh2[s * 32 + k] * sW4[k * 5 + jo];
        so[tid] = acc;
    }
    __syncthreads();
    if (tid < NPB) {
        int n = nodeBase + tid;
        float y0 = so[tid * 5 + 0];
        float c1 = so[tid * 5 + 1];
        float c2 = so[tid * 5 + 2];
        float c3 = so[tid * 5 + 3];
        float c4 = so[tid * 5 + 4];
        float nor = sqrtf(c1 * c1 + c2 * c2 + c3 * c3 + c4 * c4);
        float dd = fmaxf(1.f, nor);
        float y1 = c1 / dd, y2 = c2 / dd, y3 = c3 / dd, y4 = c4 / dd;
        float y5 = sxn[tid * F_IN + 0];
        float y6 = sxn[tid * F_IN + 1];
        float y7 = sxn[tid * F_IN + 2];
        float* yr = y + (long long)n * F_IN;
        yr[0] = y0; yr[1] = y1; yr[2] = y2; yr[3] = y3;
        yr[4] = y4; yr[5] = y5; yr[6] = y6; yr[7] = y7;
        // fp16 image for the next iteration (split once per node, not per edge)
        uint4 xs;
        xs.x = f16_pack(y1, y0);
        xs.y = f16_pack(y3, y2);
        xs.z = f16_pack(y5, y4);
        xs.w = f16_pack(y7, y6);
        xs_out[n] = xs;
    }
}

// ---------------- host ----------------
extern "C" void kernel_launch(void* const* d_in, const int* in_sizes, int n_in,
                              void* d_out, int out_size) {
    const float* x_in = (const float*)d_in[0];
    const float* ea   = (const float*)d_in[1];
    const int*   ei   = (const int*)d_in[2];
    const float* w10  = (const float*)d_in[3];
    const float* b10  = (const float*)d_in[4];
    const float* w11  = (const float*)d_in[5];
    const float* b11  = (const float*)d_in[6];
    const float* w20  = (const float*)d_in[7];
    const float* b20  = (const float*)d_in[8];
    const float* w21  = (const float*)d_in[9];
    const float* b21  = (const float*)d_in[10];

    float* xb[2];
    cudaGetSymbolAddress((void**)&xb[0], g_x0);
    cudaGetSymbolAddress((void**)&xb[1], g_x1);
    uint4* xs[2];
    cudaGetSymbolAddress((void**)&xs[0], g_xsA);
    cudaGetSymbolAddress((void**)&xs[1], g_xsB);

    const int dyn_bytes = DYN_UINTS * sizeof(unsigned);   // 32 KB
    cudaFuncSetAttribute(fused_kernel, cudaFuncAttributeMaxDynamicSharedMemorySize, dyn_bytes);

    // exactly 3 pre-launches so the profiler's captured launch (#4) is fused_kernel
    prep_kernel<<<(N_EDGES + 255) / 256, 256>>>(x_in, w10, b10, w11, ei);
    scan_kernel<<<1, 512>>>();
    scatter_kernel<<<(N_EDGES + 255) / 256, 256>>>(ea, ei);

    const float* xin = x_in;
    for (int it = 0; it < N_ITERS; it++) {
        float* yout = (it == N_ITERS - 1) ? (float*)d_out : xb[it & 1];
        fused_kernel<<<NBLK, TPB, dyn_bytes>>>(xin, xs[it & 1], yout, xs[(it + 1) & 1],
                                               b11, w20, b20, w21, b21);
        xin = yout;
    }
}